// round 1
// baseline (speedup 1.0000x reference)
#include <cuda_runtime.h>
#include <cuda_bf16.h>
#include <cstdint>

// Problem constants
#define BB 2048
#define NN 128
#define DD 512
#define EE 64
#define ROWS (BB*NN)            // 262144
#define EPS 1e-6f
#define CAPACITY 2048.0f

// Kernel-1 tiling
#define TILE_R 128
#define THREADS1 256
#define KCHUNK 32
#define NCHUNKS (DD/KCHUNK)     // 16
#define KP_CHUNK (KCHUNK/2)     // 16
#define WS_STRIDE 65            // padded to kill STS bank conflicts
#define WS_ULL (256*WS_STRIDE)  // f32x2 entries for W
#define XS_ULL (2*KP_CHUNK*TILE_R)
#define SMEM_BYTES ((WS_ULL + XS_ULL) * 8)

// Scratch (device globals; no allocation allowed)
__device__ float g_p0[ROWS];
__device__ int   g_idx[ROWS];
__device__ float g_masked[BB*EE];
__device__ float g_denom[EE];
__device__ int   g_load[EE];

// ---------------- f32x2 helpers ----------------
__device__ __forceinline__ unsigned long long pack2(float lo, float hi) {
    unsigned long long r;
    asm("mov.b64 %0, {%1, %2};" : "=l"(r) : "f"(lo), "f"(hi));
    return r;
}
__device__ __forceinline__ void unpack2(unsigned long long v, float& lo, float& hi) {
    asm("mov.b64 {%0, %1}, %2;" : "=f"(lo), "=f"(hi) : "l"(v));
}
__device__ __forceinline__ unsigned long long fma2(unsigned long long a,
                                                   unsigned long long b,
                                                   unsigned long long c) {
    unsigned long long d;
    asm("fma.rn.f32x2 %0, %1, %2, %3;" : "=l"(d) : "l"(a), "l"(b), "l"(c));
    return d;
}

// ---------------- Kernel 1: fused GEMM + softmax stats ----------------
// Each CTA: 128 rows x 64 experts. Threads (16 tx) x (16 ty):
//   ty -> 8 rows (ty*8..ty*8+7), tx -> 4 experts (tx, tx+16, tx+32, tx+48)
__global__ __launch_bounds__(THREADS1, 1)
void k1_gemm_softmax(const float* __restrict__ x,
                     const float* __restrict__ w,
                     const float* __restrict__ bias) {
    extern __shared__ unsigned long long sm[];
    unsigned long long* w_s = sm;              // [256 kpairs][65]
    unsigned long long* x_s = sm + WS_ULL;     // [2][16 kpairs][128 rows]

    const int tid = threadIdx.x;
    const int tx = tid & 15;
    const int ty = tid >> 4;
    const long rowbase = (long)blockIdx.x * TILE_R;

    // Load full W into smem as [kpair][expert] f32x2, padded stride 65.
    for (int i = tid; i < 256 * EE; i += THREADS1) {
        int kp = i & 255;
        int e  = i >> 8;
        float2 wv = *reinterpret_cast<const float2*>(w + (size_t)e * DD + kp * 2);
        w_s[kp * WS_STRIDE + e] = pack2(wv.x, wv.y);
    }

    // x streaming assignment: 2 threads per row, 4 float4 each per chunk
    const int r_ld = tid >> 1;      // 0..127
    const int half = tid & 1;
    const float4* xg = reinterpret_cast<const float4*>(x + (rowbase + r_ld) * (size_t)DD);

    unsigned long long acc[8][4];
#pragma unroll
    for (int i = 0; i < 8; i++)
#pragma unroll
        for (int j = 0; j < 4; j++) acc[i][j] = 0ull;

    float4 stg[4];
    // prologue: chunk 0
#pragma unroll
    for (int i = 0; i < 4; i++) stg[i] = xg[half * 4 + i];
#pragma unroll
    for (int i = 0; i < 4; i++) {
        int kp = half * 8 + i * 2;
        x_s[kp * TILE_R + r_ld]       = pack2(stg[i].x, stg[i].y);
        x_s[(kp + 1) * TILE_R + r_ld] = pack2(stg[i].z, stg[i].w);
    }
    __syncthreads();

    for (int c = 0; c < NCHUNKS; c++) {
        const int buf = c & 1;
        if (c < NCHUNKS - 1) {
#pragma unroll
            for (int i = 0; i < 4; i++) stg[i] = xg[(c + 1) * 8 + half * 4 + i];
        }
        const unsigned long long* xb = x_s + buf * (KP_CHUNK * TILE_R);
        const unsigned long long* wb = w_s + (c * KP_CHUNK) * WS_STRIDE;
#pragma unroll 4
        for (int kp = 0; kp < KP_CHUNK; kp++) {
            unsigned long long xv[8], wv[4];
#pragma unroll
            for (int i = 0; i < 8; i++) xv[i] = xb[kp * TILE_R + ty * 8 + i];
#pragma unroll
            for (int j = 0; j < 4; j++) wv[j] = wb[kp * WS_STRIDE + tx + 16 * j];
#pragma unroll
            for (int i = 0; i < 8; i++)
#pragma unroll
                for (int j = 0; j < 4; j++)
                    acc[i][j] = fma2(xv[i], wv[j], acc[i][j]);
        }
        if (c < NCHUNKS - 1) {
            unsigned long long* xn = x_s + (buf ^ 1) * (KP_CHUNK * TILE_R);
#pragma unroll
            for (int i = 0; i < 4; i++) {
                int kp = half * 8 + i * 2;
                xn[kp * TILE_R + r_ld]       = pack2(stg[i].x, stg[i].y);
                xn[(kp + 1) * TILE_R + r_ld] = pack2(stg[i].z, stg[i].w);
            }
        }
        __syncthreads();
    }

    // epilogue: per-row max/argmax/sumexp reductions across the 16 tx lanes
    float bb[4];
#pragma unroll
    for (int j = 0; j < 4; j++) bb[j] = __ldg(bias + tx + 16 * j);

#pragma unroll
    for (int i = 0; i < 8; i++) {
        float l[4];
#pragma unroll
        for (int j = 0; j < 4; j++) {
            float lo, hi;
            unpack2(acc[i][j], lo, hi);
            l[j] = lo + hi + bb[j];
        }
        float bv = l[0];
        int   be = tx;
#pragma unroll
        for (int j = 1; j < 4; j++) {
            int e = tx + 16 * j;
            if (l[j] > bv) { bv = l[j]; be = e; }
        }
#pragma unroll
        for (int off = 1; off < 16; off <<= 1) {
            float ov = __shfl_xor_sync(0xffffffffu, bv, off);
            int   oe = __shfl_xor_sync(0xffffffffu, be, off);
            if (ov > bv || (ov == bv && oe < be)) { bv = ov; be = oe; }
        }
        float s = 0.f;
#pragma unroll
        for (int j = 0; j < 4; j++) s += __expf(l[j] - bv);
#pragma unroll
        for (int off = 1; off < 16; off <<= 1)
            s += __shfl_xor_sync(0xffffffffu, s, off);

        if (tx == 0) {
            long row = rowbase + ty * 8 + i;
            g_p0[row]  = __expf(l[0] - bv) / s;   // prob of expert 0
            g_idx[row] = be;                       // argmax expert
        }
    }
}

// ---------------- Kernel 2: per-batch membership mask -> masked p0 ----------------
// One warp per batch b. mask bit n set iff any position's argmax == n.
__global__ void k2_mask(void) {
    int b    = blockIdx.x * 8 + (threadIdx.x >> 5);
    int lane = threadIdx.x & 31;
    long base = (long)b * NN;
    unsigned long long m = 0ull;
#pragma unroll
    for (int q = 0; q < 4; q++) {
        int v = g_idx[base + lane + 32 * q];
        m |= 1ull << v;
    }
#pragma unroll
    for (int off = 16; off >= 1; off >>= 1)
        m |= __shfl_xor_sync(0xffffffffu, m, off);
#pragma unroll
    for (int h = 0; h < 2; h++) {
        int n = lane + 32 * h;
        g_masked[b * EE + n] = ((m >> n) & 1ull) ? g_p0[base + n] : 0.f;
    }
}

// ---------------- Kernel 3: deterministic column sums (denom, load) ----------------
__global__ void k3_denom(void) {
    __shared__ float sv[256];
    __shared__ int   sc[256];
    int n = blockIdx.x;
    int t = threadIdx.x;
    float s = 0.f;
    int cnt = 0;
    for (int k = 0; k < BB / 256; k++) {
        float v = g_masked[(size_t)(t + k * 256) * EE + n];
        s += v;
        cnt += (v > 0.f);
    }
    sv[t] = s; sc[t] = cnt;
    __syncthreads();
    for (int off = 128; off >= 1; off >>= 1) {
        if (t < off) { sv[t] += sv[t + off]; sc[t] += sc[t + off]; }
        __syncthreads();
    }
    if (t == 0) {
        g_denom[n] = sv[0] + EPS;
        g_load[n]  = sc[0];
    }
}

// ---------------- Kernel 4: write gs (mostly zeros, sparse column e==0) ----------------
__global__ void k4_write(float4* __restrict__ out) {
    long i4 = (long)blockIdx.x * blockDim.x + threadIdx.x;
    int e4 = (int)(i4 & 15);          // float4 index within E (e = e4*4)
    long rem = i4 >> 4;
    int n = (int)(rem & (NN - 1));
    long b = rem >> 7;
    float4 v = make_float4(0.f, 0.f, 0.f, 0.f);
    if (e4 == 0 && n < EE) {
        float m = g_masked[b * EE + n];
        v.x = m * (CAPACITY / g_denom[n]);
    }
    out[i4] = v;
}

// ---------------- Kernel 5: loss ----------------
__global__ void k5_loss(float* __restrict__ lossptr) {
    double si = 0.0, si2 = 0.0, sl = 0.0, sl2 = 0.0;
    for (int n = 0; n < EE; n++) {
        double dn = (double)g_denom[n];
        double S  = dn - (double)EPS;
        double imp = (double)CAPACITY * S / dn;   // sum_b gs[b,n,0]
        si  += imp;
        si2 += imp * imp;
        double ld = (double)g_load[n];
        sl  += ld;
        sl2 += ld * ld;
    }
    const double M = (double)(NN * EE);           // 8192 flattened elements
    double mean_i = si / M;
    double var_i  = (si2 - si * si / M) / (M - 1.0);
    double cv_i   = var_i / (mean_i * mean_i + 1e-10);
    double mean_l = sl / M;
    double var_l  = (sl2 - sl * sl / M) / (M - 1.0);
    double cv_l   = var_l / (mean_l * mean_l + 1e-10);
    *lossptr = (float)(cv_i + cv_l);
}

extern "C" void kernel_launch(void* const* d_in, const int* in_sizes, int n_in,
                              void* d_out, int out_size) {
    const float* x    = (const float*)d_in[0];
    const float* w    = (const float*)d_in[1];
    const float* bias = (const float*)d_in[2];
    float* out = (float*)d_out;

    cudaFuncSetAttribute(k1_gemm_softmax,
                         cudaFuncAttributeMaxDynamicSharedMemorySize, SMEM_BYTES);

    k1_gemm_softmax<<<ROWS / TILE_R, THREADS1, SMEM_BYTES>>>(x, w, bias);
    k2_mask<<<BB / 8, 256>>>();
    k3_denom<<<EE, 256>>>();

    const long total = (long)BB * NN * EE;        // 16777216
    if ((long)out_size >= total) {
        k4_write<<<(int)(total / 4 / 256), 256>>>((float4*)out);
    }
    if ((long)out_size > total) {
        k5_loss<<<1, 1>>>(out + total);
    } else if ((long)out_size < total) {
        // output carries only the loss scalar
        k5_loss<<<1, 1>>>(out);
    }
}

// round 2
// speedup vs baseline: 1.0001x; 1.0001x over previous
#include <cuda_runtime.h>
#include <cuda_bf16.h>
#include <cstdint>

// Problem constants
#define BB 2048
#define NN 128
#define DD 512
#define EE 64
#define ROWS (BB*NN)            // 262144
#define EPS 1e-6f
#define CAPACITY 2048.0f

// Kernel-1 tiling
#define TILE_R 128
#define THREADS1 256
#define KCHUNK 32
#define NCHUNKS (DD/KCHUNK)     // 16
#define KP_CHUNK (KCHUNK/2)     // 16
#define WS_STRIDE 65            // padded to kill STS bank conflicts
#define WS_ULL (256*WS_STRIDE)  // f32x2 entries for W
#define XS_ULL (2*KP_CHUNK*TILE_R)
#define SMEM_BYTES ((WS_ULL + XS_ULL) * 8)

// Scratch (device globals; no allocation allowed)
__device__ float g_p0[ROWS];
__device__ int   g_idx[ROWS];
__device__ float g_masked[BB*EE];
__device__ float g_denom[EE];
__device__ int   g_load[EE];

// ---------------- f32x2 helpers ----------------
__device__ __forceinline__ unsigned long long pack2(float lo, float hi) {
    unsigned long long r;
    asm("mov.b64 %0, {%1, %2};" : "=l"(r) : "f"(lo), "f"(hi));
    return r;
}
__device__ __forceinline__ void unpack2(unsigned long long v, float& lo, float& hi) {
    asm("mov.b64 {%0, %1}, %2;" : "=f"(lo), "=f"(hi) : "l"(v));
}
__device__ __forceinline__ unsigned long long fma2(unsigned long long a,
                                                   unsigned long long b,
                                                   unsigned long long c) {
    unsigned long long d;
    asm("fma.rn.f32x2 %0, %1, %2, %3;" : "=l"(d) : "l"(a), "l"(b), "l"(c));
    return d;
}

// ---------------- Kernel 1: fused GEMM + softmax stats ----------------
// Each CTA: 128 rows x 64 experts. Threads (16 tx) x (16 ty):
//   ty -> 8 rows (ty*8..ty*8+7), tx -> 4 experts (tx, tx+16, tx+32, tx+48)
__global__ __launch_bounds__(THREADS1, 1)
void k1_gemm_softmax(const float* __restrict__ x,
                     const float* __restrict__ w,
                     const float* __restrict__ bias) {
    extern __shared__ unsigned long long sm[];
    unsigned long long* w_s = sm;              // [256 kpairs][65]
    unsigned long long* x_s = sm + WS_ULL;     // [2][16 kpairs][128 rows]

    const int tid = threadIdx.x;
    const int tx = tid & 15;
    const int ty = tid >> 4;
    const long rowbase = (long)blockIdx.x * TILE_R;

    // Load full W into smem as [kpair][expert] f32x2, padded stride 65.
    for (int i = tid; i < 256 * EE; i += THREADS1) {
        int kp = i & 255;
        int e  = i >> 8;
        float2 wv = *reinterpret_cast<const float2*>(w + (size_t)e * DD + kp * 2);
        w_s[kp * WS_STRIDE + e] = pack2(wv.x, wv.y);
    }

    // x streaming assignment: 2 threads per row, 4 float4 each per chunk
    const int r_ld = tid >> 1;      // 0..127
    const int half = tid & 1;
    const float4* xg = reinterpret_cast<const float4*>(x + (rowbase + r_ld) * (size_t)DD);

    unsigned long long acc[8][4];
#pragma unroll
    for (int i = 0; i < 8; i++)
#pragma unroll
        for (int j = 0; j < 4; j++) acc[i][j] = 0ull;

    float4 stg[4];
    // prologue: chunk 0
#pragma unroll
    for (int i = 0; i < 4; i++) stg[i] = xg[half * 4 + i];
#pragma unroll
    for (int i = 0; i < 4; i++) {
        int kp = half * 8 + i * 2;
        x_s[kp * TILE_R + r_ld]       = pack2(stg[i].x, stg[i].y);
        x_s[(kp + 1) * TILE_R + r_ld] = pack2(stg[i].z, stg[i].w);
    }
    __syncthreads();

    for (int c = 0; c < NCHUNKS; c++) {
        const int buf = c & 1;
        if (c < NCHUNKS - 1) {
#pragma unroll
            for (int i = 0; i < 4; i++) stg[i] = xg[(c + 1) * 8 + half * 4 + i];
        }
        const unsigned long long* xb = x_s + buf * (KP_CHUNK * TILE_R);
        const unsigned long long* wb = w_s + (c * KP_CHUNK) * WS_STRIDE;
#pragma unroll 4
        for (int kp = 0; kp < KP_CHUNK; kp++) {
            unsigned long long xv[8], wv[4];
#pragma unroll
            for (int i = 0; i < 8; i++) xv[i] = xb[kp * TILE_R + ty * 8 + i];
#pragma unroll
            for (int j = 0; j < 4; j++) wv[j] = wb[kp * WS_STRIDE + tx + 16 * j];
#pragma unroll
            for (int i = 0; i < 8; i++)
#pragma unroll
                for (int j = 0; j < 4; j++)
                    acc[i][j] = fma2(xv[i], wv[j], acc[i][j]);
        }
        if (c < NCHUNKS - 1) {
            unsigned long long* xn = x_s + (buf ^ 1) * (KP_CHUNK * TILE_R);
#pragma unroll
            for (int i = 0; i < 4; i++) {
                int kp = half * 8 + i * 2;
                xn[kp * TILE_R + r_ld]       = pack2(stg[i].x, stg[i].y);
                xn[(kp + 1) * TILE_R + r_ld] = pack2(stg[i].z, stg[i].w);
            }
        }
        __syncthreads();
    }

    // epilogue: per-row max/argmax/sumexp reductions across the 16 tx lanes
    float bb[4];
#pragma unroll
    for (int j = 0; j < 4; j++) bb[j] = __ldg(bias + tx + 16 * j);

#pragma unroll
    for (int i = 0; i < 8; i++) {
        float l[4];
#pragma unroll
        for (int j = 0; j < 4; j++) {
            float lo, hi;
            unpack2(acc[i][j], lo, hi);
            l[j] = lo + hi + bb[j];
        }
        float bv = l[0];
        int   be = tx;
#pragma unroll
        for (int j = 1; j < 4; j++) {
            int e = tx + 16 * j;
            if (l[j] > bv) { bv = l[j]; be = e; }
        }
#pragma unroll
        for (int off = 1; off < 16; off <<= 1) {
            float ov = __shfl_xor_sync(0xffffffffu, bv, off);
            int   oe = __shfl_xor_sync(0xffffffffu, be, off);
            if (ov > bv || (ov == bv && oe < be)) { bv = ov; be = oe; }
        }
        float s = 0.f;
#pragma unroll
        for (int j = 0; j < 4; j++) s += __expf(l[j] - bv);
#pragma unroll
        for (int off = 1; off < 16; off <<= 1)
            s += __shfl_xor_sync(0xffffffffu, s, off);

        if (tx == 0) {
            long row = rowbase + ty * 8 + i;
            g_p0[row]  = __expf(l[0] - bv) / s;   // prob of expert 0
            g_idx[row] = be;                       // argmax expert
        }
    }
}

// ---------------- Kernel 2: per-batch membership mask -> masked p0 ----------------
// One warp per batch b. mask bit n set iff any position's argmax == n.
__global__ void k2_mask(void) {
    int b    = blockIdx.x * 8 + (threadIdx.x >> 5);
    int lane = threadIdx.x & 31;
    long base = (long)b * NN;
    unsigned long long m = 0ull;
#pragma unroll
    for (int q = 0; q < 4; q++) {
        int v = g_idx[base + lane + 32 * q];
        m |= 1ull << v;
    }
#pragma unroll
    for (int off = 16; off >= 1; off >>= 1)
        m |= __shfl_xor_sync(0xffffffffu, m, off);
#pragma unroll
    for (int h = 0; h < 2; h++) {
        int n = lane + 32 * h;
        g_masked[b * EE + n] = ((m >> n) & 1ull) ? g_p0[base + n] : 0.f;
    }
}

// ---------------- Kernel 3: deterministic column sums (denom, load) ----------------
__global__ void k3_denom(void) {
    __shared__ float sv[256];
    __shared__ int   sc[256];
    int n = blockIdx.x;
    int t = threadIdx.x;
    float s = 0.f;
    int cnt = 0;
    for (int k = 0; k < BB / 256; k++) {
        float v = g_masked[(size_t)(t + k * 256) * EE + n];
        s += v;
        cnt += (v > 0.f);
    }
    sv[t] = s; sc[t] = cnt;
    __syncthreads();
    for (int off = 128; off >= 1; off >>= 1) {
        if (t < off) { sv[t] += sv[t + off]; sc[t] += sc[t + off]; }
        __syncthreads();
    }
    if (t == 0) {
        g_denom[n] = sv[0] + EPS;
        g_load[n]  = sc[0];
    }
}

// ---------------- Kernel 4: write gs (mostly zeros, sparse column e==0) ----------------
__global__ void k4_write(float4* __restrict__ out) {
    long i4 = (long)blockIdx.x * blockDim.x + threadIdx.x;
    int e4 = (int)(i4 & 15);          // float4 index within E (e = e4*4)
    long rem = i4 >> 4;
    int n = (int)(rem & (NN - 1));
    long b = rem >> 7;
    float4 v = make_float4(0.f, 0.f, 0.f, 0.f);
    if (e4 == 0 && n < EE) {
        float m = g_masked[b * EE + n];
        v.x = m * (CAPACITY / g_denom[n]);
    }
    out[i4] = v;
}

// ---------------- Kernel 5: loss ----------------
__global__ void k5_loss(float* __restrict__ lossptr) {
    double si = 0.0, si2 = 0.0, sl = 0.0, sl2 = 0.0;
    for (int n = 0; n < EE; n++) {
        double dn = (double)g_denom[n];
        double S  = dn - (double)EPS;
        double imp = (double)CAPACITY * S / dn;   // sum_b gs[b,n,0]
        si  += imp;
        si2 += imp * imp;
        double ld = (double)g_load[n];
        sl  += ld;
        sl2 += ld * ld;
    }
    const double M = (double)(NN * EE);           // 8192 flattened elements
    double mean_i = si / M;
    double var_i  = (si2 - si * si / M) / (M - 1.0);
    double cv_i   = var_i / (mean_i * mean_i + 1e-10);
    double mean_l = sl / M;
    double var_l  = (sl2 - sl * sl / M) / (M - 1.0);
    double cv_l   = var_l / (mean_l * mean_l + 1e-10);
    *lossptr = (float)(cv_i + cv_l);
}

extern "C" void kernel_launch(void* const* d_in, const int* in_sizes, int n_in,
                              void* d_out, int out_size) {
    const float* x    = (const float*)d_in[0];
    const float* w    = (const float*)d_in[1];
    const float* bias = (const float*)d_in[2];
    float* out = (float*)d_out;

    cudaFuncSetAttribute(k1_gemm_softmax,
                         cudaFuncAttributeMaxDynamicSharedMemorySize, SMEM_BYTES);

    k1_gemm_softmax<<<ROWS / TILE_R, THREADS1, SMEM_BYTES>>>(x, w, bias);
    k2_mask<<<BB / 8, 256>>>();
    k3_denom<<<EE, 256>>>();

    const long total = (long)BB * NN * EE;        // 16777216
    if ((long)out_size >= total) {
        k4_write<<<(int)(total / 4 / 256), 256>>>((float4*)out);
    }
    if ((long)out_size > total) {
        k5_loss<<<1, 1>>>(out + total);
    } else if ((long)out_size < total) {
        // output carries only the loss scalar
        k5_loss<<<1, 1>>>(out);
    }
}

// round 4
// speedup vs baseline: 1.1006x; 1.1005x over previous
#include <cuda_runtime.h>
#include <cuda_bf16.h>
#include <cstdint>

// Problem constants
#define BB 2048
#define NN 128
#define DD 512
#define EE 64
#define ROWS (BB*NN)            // 262144
#define EPS 1e-6f
#define CAPACITY 2048.0f

#define TILE_M 128
#define THREADS1 256

// ---- tcgen05 path tiling ----
#define KC 64                   // K per chunk (64 bf16 = 128B rows, SW128)
#define NCH (DD/KC)             // 8 chunks
#define A_TILE_B (TILE_M*128)   // 16384 per term
#define B_TILE_B (EE*128)       // 8192 per term
#define A_BUF_B (3*A_TILE_B)    // 49152 per buffer
#define B_BUF_B (3*B_TILE_B)    // 24576 per buffer
#define TILES_B (2*A_BUF_B + 2*B_BUF_B)   // 147456
#define SMEM_TC (2048 + TILES_B)          // 149504

// ---- fp32 FMA fallback tiling ----
#define KCHUNK 32
#define NCHUNKS (DD/KCHUNK)     // 16
#define KP_CHUNK (KCHUNK/2)     // 16
#define WS_STRIDE 65
#define WS_ULL (256*WS_STRIDE)
#define XS_ULL (2*KP_CHUNK*TILE_M)
#define SMEM_FMA ((WS_ULL + XS_ULL) * 8)  // 165888

#define SMEM_MAX (SMEM_FMA > SMEM_TC ? SMEM_FMA : SMEM_TC)

// idesc: dtype=F32, atype=BF16, btype=BF16, N=64, M=128, K-major both
#define IDESC ((1u<<4)|(1u<<7)|(1u<<10)|((EE/8)<<17)|((TILE_M/16)<<24))

// Scratch (device globals; no allocation allowed)
__device__ float g_p0[ROWS];
__device__ int   g_idx[ROWS];
__device__ float g_masked[BB*EE];
__device__ float g_denom[EE];
__device__ int   g_load[EE];
__device__ __nv_bfloat16 g_wh[EE*DD];
__device__ __nv_bfloat16 g_wm[EE*DD];
__device__ __nv_bfloat16 g_wl[EE*DD];

#define HAS_TCGEN05 (defined(__CUDA_ARCH_FEAT_SM103_ALL) || defined(__CUDA_ARCH_FEAT_SM100_ALL) || defined(__CUDA_ARCH_FEAT_SM101_ALL))

// ---------------- generic helpers ----------------
__device__ __forceinline__ uint32_t sw128(uint32_t o) { return o ^ ((o >> 3) & 0x70); }

__device__ __forceinline__ uint32_t pack_bf2(__nv_bfloat16 a, __nv_bfloat16 b) {
    __nv_bfloat162 t = __halves2bfloat162(a, b);
    return *reinterpret_cast<uint32_t*>(&t);
}
__device__ __forceinline__ unsigned long long pack2(float lo, float hi) {
    unsigned long long r;
    asm("mov.b64 %0, {%1, %2};" : "=l"(r) : "f"(lo), "f"(hi));
    return r;
}
__device__ __forceinline__ void unpack2(unsigned long long v, float& lo, float& hi) {
    asm("mov.b64 {%0, %1}, %2;" : "=f"(lo), "=f"(hi) : "l"(v));
}
__device__ __forceinline__ unsigned long long fma2(unsigned long long a,
                                                   unsigned long long b,
                                                   unsigned long long c) {
    unsigned long long d;
    asm("fma.rn.f32x2 %0, %1, %2, %3;" : "=l"(d) : "l"(a), "l"(b), "l"(c));
    return d;
}

#if HAS_TCGEN05
// ---------------- tcgen05 PTX helpers (arch-specific target only) ----------------
__device__ __forceinline__ uint32_t smem_u32(const void* p) {
    uint32_t a;
    asm("{ .reg .u64 t; cvta.to.shared.u64 t, %1; cvt.u32.u64 %0, t; }"
        : "=r"(a) : "l"(p));
    return a;
}
__device__ __forceinline__ uint32_t elect1() {
    uint32_t r;
    asm volatile("{\n\t.reg .pred p;\n\telect.sync _|p, 0xFFFFFFFF;\n\t"
                 "selp.b32 %0, 1, 0, p;\n\t}" : "=r"(r));
    return r;
}
__device__ __forceinline__ uint64_t make_desc_sw128(uint32_t addr) {
    const uint64_t base = (2ull << 61) | (1ull << 46) | (64ull << 32) | (1ull << 16);
    return base | ((uint64_t)(addr >> 4) & 0x3FFF);
}
__device__ __forceinline__ void mma_ss_f16(uint32_t d, uint64_t a, uint64_t b,
                                           uint32_t idesc, uint32_t en) {
    asm volatile(
        "{\n\t.reg .pred p;\n\tsetp.ne.u32 p, %4, 0;\n\t"
        "tcgen05.mma.cta_group::1.kind::f16 [%0], %1, %2, %3, {%5,%5,%5,%5}, p;\n\t}"
        :: "r"(d), "l"(a), "l"(b), "r"(idesc), "r"(en), "r"(0u) : "memory");
}
__device__ __forceinline__ void mbar_init(uint32_t a, uint32_t cnt) {
    asm volatile("mbarrier.init.shared.b64 [%0], %1;" :: "r"(a), "r"(cnt) : "memory");
}
__device__ __forceinline__ void mbar_wait(uint32_t a, uint32_t parity) {
    uint32_t done;
    asm volatile("{\n\t.reg .pred p;\n\t"
        "mbarrier.try_wait.parity.acquire.cta.shared::cta.b64 p, [%1], %2;\n\t"
        "selp.b32 %0, 1, 0, p;\n\t}" : "=r"(done) : "r"(a), "r"(parity) : "memory");
    while (!done) {
        asm volatile("{\n\t.reg .pred p;\n\t"
            "mbarrier.try_wait.parity.acquire.cta.shared::cta.b64 p, [%1], %2, 0x989680;\n\t"
            "selp.b32 %0, 1, 0, p;\n\t}" : "=r"(done) : "r"(a), "r"(parity) : "memory");
    }
}
__device__ __forceinline__ void t5_commit(uint32_t mb) {
    asm volatile("tcgen05.commit.cta_group::1.mbarrier::arrive::one.shared::cluster.b64 [%0];"
                 :: "r"(mb) : "memory");
}
#define T5_ALLOC(smaddr, n) \
    asm volatile("tcgen05.alloc.cta_group::1.sync.aligned.shared::cta.b32 [%0], %1;" \
                 :: "r"(smaddr), "r"((uint32_t)(n)) : "memory")
#define T5_RELINQ() \
    asm volatile("tcgen05.relinquish_alloc_permit.cta_group::1.sync.aligned;")
#define T5_DEALLOC(t, n) \
    asm volatile("tcgen05.dealloc.cta_group::1.sync.aligned.b32 %0, %1;" :: "r"(t), "r"((uint32_t)(n)))
#define T5_FENCE_AFTER()  asm volatile("tcgen05.fence::after_thread_sync;" ::: "memory")
#define T5_FENCE_BEFORE() asm volatile("tcgen05.fence::before_thread_sync;" ::: "memory")
#define T5_WAIT_LD()      asm volatile("tcgen05.wait::ld.sync.aligned;" ::: "memory")
#define FENCE_ASYNC()     asm volatile("fence.proxy.async.shared::cta;" ::: "memory")

#define LDTM32(r, addr) \
    asm volatile( \
        "tcgen05.ld.sync.aligned.32x32b.x32.b32 " \
        "{%0, %1, %2, %3, %4, %5, %6, %7, " \
        " %8, %9, %10, %11, %12, %13, %14, %15, " \
        " %16, %17, %18, %19, %20, %21, %22, %23, " \
        " %24, %25, %26, %27, %28, %29, %30, %31}, [%32];" \
        : "=r"((r)[0]),  "=r"((r)[1]),  "=r"((r)[2]),  "=r"((r)[3]), \
          "=r"((r)[4]),  "=r"((r)[5]),  "=r"((r)[6]),  "=r"((r)[7]), \
          "=r"((r)[8]),  "=r"((r)[9]),  "=r"((r)[10]), "=r"((r)[11]), \
          "=r"((r)[12]), "=r"((r)[13]), "=r"((r)[14]), "=r"((r)[15]), \
          "=r"((r)[16]), "=r"((r)[17]), "=r"((r)[18]), "=r"((r)[19]), \
          "=r"((r)[20]), "=r"((r)[21]), "=r"((r)[22]), "=r"((r)[23]), \
          "=r"((r)[24]), "=r"((r)[25]), "=r"((r)[26]), "=r"((r)[27]), \
          "=r"((r)[28]), "=r"((r)[29]), "=r"((r)[30]), "=r"((r)[31]) \
        : "r"(addr))
#endif  // HAS_TCGEN05

// ---------------- Kernel 0: split W fp32 -> 3x bf16 ----------------
__global__ void k0_wsplit(const float* __restrict__ w) {
    int i = blockIdx.x * blockDim.x + threadIdx.x;   // 0..32767
    float v = w[i];
    __nv_bfloat16 h = __float2bfloat16(v);
    float r1 = v - __bfloat162float(h);
    __nv_bfloat16 m = __float2bfloat16(r1);
    float r2 = r1 - __bfloat162float(m);
    __nv_bfloat16 l = __float2bfloat16(r2);
    g_wh[i] = h; g_wm[i] = m; g_wl[i] = l;
}

// ---------------- Kernel 1: GEMM + softmax stats ----------------
// tcgen05 path on sm_103a-specific target; fp32 FMA2 fallback elsewhere.
__global__ __launch_bounds__(THREADS1, 1)
void k1_gemm(const float* __restrict__ x,
             const float* __restrict__ w,
             const float* __restrict__ bias) {
#if HAS_TCGEN05
    extern __shared__ char sm[];
    const uint32_t smem_base = smem_u32(sm);
    const uint32_t mb0 = smem_base + 16;
    const uint32_t mb1 = smem_base + 24;
    float* bias_s = reinterpret_cast<float*>(sm + 64);
    const uint32_t tiles = (smem_base + 1024 + 1023) & ~1023u;
    char* tbase = sm + (tiles - smem_base);

    const int tid = threadIdx.x;
    const int wid = tid >> 5, lid = tid & 31;
    const long rowbase = (long)blockIdx.x * TILE_M;

    if (wid == 0) {
        T5_ALLOC(smem_base, 128);
        T5_RELINQ();
    }
    if (tid == 0) { mbar_init(mb0, 1); mbar_init(mb1, 1); }
    if (tid < EE) bias_s[tid] = bias[tid];
    __syncthreads();
    const uint32_t tmem = *reinterpret_cast<uint32_t*>(sm);

    // converter mapping for A: 2 threads per row, 32 k each
    const int row = tid >> 1;
    const int half = tid & 1;
    const float4* xg = reinterpret_cast<const float4*>(x + (rowbase + row) * (size_t)DD);
    const uint32_t arow_off = (uint32_t)row * 128 + half * 64;

    for (int c = 0; c < NCH; c++) {
        const int buf = c & 1;
        if (c >= 2) mbar_wait(buf ? mb1 : mb0, ((c >> 1) - 1) & 1);

        // --- convert x chunk -> 3 bf16 A tiles (swizzled) ---
        char* ah = tbase + buf * A_BUF_B;
        char* am = ah + A_TILE_B;
        char* al = am + A_TILE_B;
#pragma unroll
        for (int i = 0; i < 8; i++) {
            float4 v = xg[c * 16 + half * 8 + i];
            float f[4] = {v.x, v.y, v.z, v.w};
            __nv_bfloat16 h[4], m[4], l[4];
#pragma unroll
            for (int q = 0; q < 4; q++) {
                h[q] = __float2bfloat16(f[q]);
                float r1 = f[q] - __bfloat162float(h[q]);
                m[q] = __float2bfloat16(r1);
                float r2 = r1 - __bfloat162float(m[q]);
                l[q] = __float2bfloat16(r2);
            }
            uint32_t sw = sw128(arow_off + i * 8);
            *reinterpret_cast<uint2*>(ah + sw) = make_uint2(pack_bf2(h[0], h[1]), pack_bf2(h[2], h[3]));
            *reinterpret_cast<uint2*>(am + sw) = make_uint2(pack_bf2(m[0], m[1]), pack_bf2(m[2], m[3]));
            *reinterpret_cast<uint2*>(al + sw) = make_uint2(pack_bf2(l[0], l[1]), pack_bf2(l[2], l[3]));
        }

        // --- load W bf16 chunk -> 3 B tiles (swizzled) ---
        char* bh = tbase + 2 * A_BUF_B + buf * B_BUF_B;
        char* bm = bh + B_TILE_B;
        char* bl = bm + B_TILE_B;
        for (int j = tid; j < 1024; j += THREADS1) {
            int br = j >> 4, bk = j & 15;
            uint32_t sw = sw128((uint32_t)br * 128 + bk * 8);
            size_t gi = (size_t)br * DD + c * KC + bk * 4;
            *reinterpret_cast<uint2*>(bh + sw) = *reinterpret_cast<const uint2*>(g_wh + gi);
            *reinterpret_cast<uint2*>(bm + sw) = *reinterpret_cast<const uint2*>(g_wm + gi);
            *reinterpret_cast<uint2*>(bl + sw) = *reinterpret_cast<const uint2*>(g_wl + gi);
        }
        FENCE_ASYNC();
        __syncthreads();

        // --- issue 24 MMAs (6 term pairs x 4 k-steps) ---
        if (wid == 0) {
            if (elect1()) {
                uint64_t ad[3], bd[3];
#pragma unroll
                for (int t = 0; t < 3; t++) {
                    ad[t] = make_desc_sw128(tiles + buf * A_BUF_B + t * A_TILE_B);
                    bd[t] = make_desc_sw128(tiles + 2 * A_BUF_B + buf * B_BUF_B + t * B_TILE_B);
                }
                const int ta[6] = {0, 0, 1, 1, 0, 2};
                const int tb[6] = {0, 1, 0, 1, 2, 0};
#pragma unroll
                for (int t = 0; t < 6; t++) {
#pragma unroll
                    for (int ks = 0; ks < 4; ks++) {
                        uint32_t en = !(c == 0 && t == 0 && ks == 0);
                        mma_ss_f16(tmem, ad[ta[t]] + ks * 2, bd[tb[t]] + ks * 2, IDESC, en);
                    }
                }
                t5_commit(buf ? mb1 : mb0);
            }
        }
        __syncthreads();
    }

    // final: wait last commit (chunk 7 = 4th arrival on mb1 -> completes phase parity 1)
    mbar_wait(mb1, 1);
    T5_FENCE_AFTER();

    // epilogue: warps 0-3 read 128 rows x 64 logits from TMEM
    if (tid < 128) {
        uint32_t dr[64];
        LDTM32(dr, tmem);
        LDTM32(dr + 32, tmem + 32);
        T5_WAIT_LD();
        T5_FENCE_BEFORE();

        float vals[EE];
#pragma unroll
        for (int e = 0; e < EE; e++)
            vals[e] = __uint_as_float(dr[e]) + bias_s[e];

        float bv = vals[0];
        int be = 0;
#pragma unroll
        for (int e = 1; e < EE; e++)
            if (vals[e] > bv) { bv = vals[e]; be = e; }

        float s = 0.f;
#pragma unroll
        for (int e = 0; e < EE; e++)
            s += __expf(vals[e] - bv);

        long r = rowbase + wid * 32 + lid;
        g_p0[r]  = __expf(vals[0] - bv) / s;
        g_idx[r] = be;
    }

    __syncthreads();
    if (wid == 0) {
        T5_DEALLOC(tmem, 128);
    }
#else
    // ---------------- fp32 FMA2 fallback (proven R2 path) ----------------
    extern __shared__ unsigned long long smu[];
    unsigned long long* w_s = smu;              // [256 kpairs][65]
    unsigned long long* x_s = smu + WS_ULL;     // [2][16 kpairs][128 rows]

    const int tid = threadIdx.x;
    const int tx = tid & 15;
    const int ty = tid >> 4;
    const long rowbase = (long)blockIdx.x * TILE_M;

    for (int i = tid; i < 256 * EE; i += THREADS1) {
        int kp = i & 255;
        int e  = i >> 8;
        float2 wv = *reinterpret_cast<const float2*>(w + (size_t)e * DD + kp * 2);
        w_s[kp * WS_STRIDE + e] = pack2(wv.x, wv.y);
    }

    const int r_ld = tid >> 1;
    const int half = tid & 1;
    const float4* xg = reinterpret_cast<const float4*>(x + (rowbase + r_ld) * (size_t)DD);

    unsigned long long acc[8][4];
#pragma unroll
    for (int i = 0; i < 8; i++)
#pragma unroll
        for (int j = 0; j < 4; j++) acc[i][j] = 0ull;

    float4 stg[4];
#pragma unroll
    for (int i = 0; i < 4; i++) stg[i] = xg[half * 4 + i];
#pragma unroll
    for (int i = 0; i < 4; i++) {
        int kp = half * 8 + i * 2;
        x_s[kp * TILE_M + r_ld]       = pack2(stg[i].x, stg[i].y);
        x_s[(kp + 1) * TILE_M + r_ld] = pack2(stg[i].z, stg[i].w);
    }
    __syncthreads();

    for (int c = 0; c < NCHUNKS; c++) {
        const int buf = c & 1;
        if (c < NCHUNKS - 1) {
#pragma unroll
            for (int i = 0; i < 4; i++) stg[i] = xg[(c + 1) * 8 + half * 4 + i];
        }
        const unsigned long long* xb = x_s + buf * (KP_CHUNK * TILE_M);
        const unsigned long long* wb = w_s + (c * KP_CHUNK) * WS_STRIDE;
#pragma unroll 4
        for (int kp = 0; kp < KP_CHUNK; kp++) {
            unsigned long long xv[8], wv[4];
#pragma unroll
            for (int i = 0; i < 8; i++) xv[i] = xb[kp * TILE_M + ty * 8 + i];
#pragma unroll
            for (int j = 0; j < 4; j++) wv[j] = wb[kp * WS_STRIDE + tx + 16 * j];
#pragma unroll
            for (int i = 0; i < 8; i++)
#pragma unroll
                for (int j = 0; j < 4; j++)
                    acc[i][j] = fma2(xv[i], wv[j], acc[i][j]);
        }
        if (c < NCHUNKS - 1) {
            unsigned long long* xn = x_s + (buf ^ 1) * (KP_CHUNK * TILE_M);
#pragma unroll
            for (int i = 0; i < 4; i++) {
                int kp = half * 8 + i * 2;
                xn[kp * TILE_M + r_ld]       = pack2(stg[i].x, stg[i].y);
                xn[(kp + 1) * TILE_M + r_ld] = pack2(stg[i].z, stg[i].w);
            }
        }
        __syncthreads();
    }

    float bb[4];
#pragma unroll
    for (int j = 0; j < 4; j++) bb[j] = __ldg(bias + tx + 16 * j);

#pragma unroll
    for (int i = 0; i < 8; i++) {
        float l[4];
#pragma unroll
        for (int j = 0; j < 4; j++) {
            float lo, hi;
            unpack2(acc[i][j], lo, hi);
            l[j] = lo + hi + bb[j];
        }
        float bv = l[0];
        int   be = tx;
#pragma unroll
        for (int j = 1; j < 4; j++) {
            int e = tx + 16 * j;
            if (l[j] > bv) { bv = l[j]; be = e; }
        }
#pragma unroll
        for (int off = 1; off < 16; off <<= 1) {
            float ov = __shfl_xor_sync(0xffffffffu, bv, off);
            int   oe = __shfl_xor_sync(0xffffffffu, be, off);
            if (ov > bv || (ov == bv && oe < be)) { bv = ov; be = oe; }
        }
        float s = 0.f;
#pragma unroll
        for (int j = 0; j < 4; j++) s += __expf(l[j] - bv);
#pragma unroll
        for (int off = 1; off < 16; off <<= 1)
            s += __shfl_xor_sync(0xffffffffu, s, off);

        if (tx == 0) {
            long row = rowbase + ty * 8 + i;
            g_p0[row]  = __expf(l[0] - bv) / s;
            g_idx[row] = be;
        }
    }
#endif
}

// ---------------- Kernel 2: per-batch membership mask -> masked p0 ----------------
__global__ void k2_mask(void) {
    int b    = blockIdx.x * 8 + (threadIdx.x >> 5);
    int lane = threadIdx.x & 31;
    long base = (long)b * NN;
    unsigned long long m = 0ull;
#pragma unroll
    for (int q = 0; q < 4; q++) {
        int v = g_idx[base + lane + 32 * q];
        m |= 1ull << v;
    }
#pragma unroll
    for (int off = 16; off >= 1; off >>= 1)
        m |= __shfl_xor_sync(0xffffffffu, m, off);
#pragma unroll
    for (int h = 0; h < 2; h++) {
        int n = lane + 32 * h;
        g_masked[b * EE + n] = ((m >> n) & 1ull) ? g_p0[base + n] : 0.f;
    }
}

// ---------------- Kernel 3: deterministic column sums (denom, load) ----------------
__global__ void k3_denom(void) {
    __shared__ float sv[256];
    __shared__ int   sc[256];
    int n = blockIdx.x;
    int t = threadIdx.x;
    float s = 0.f;
    int cnt = 0;
    for (int k = 0; k < BB / 256; k++) {
        float v = g_masked[(size_t)(t + k * 256) * EE + n];
        s += v;
        cnt += (v > 0.f);
    }
    sv[t] = s; sc[t] = cnt;
    __syncthreads();
    for (int off = 128; off >= 1; off >>= 1) {
        if (t < off) { sv[t] += sv[t + off]; sc[t] += sc[t + off]; }
        __syncthreads();
    }
    if (t == 0) {
        g_denom[n] = sv[0] + EPS;
        g_load[n]  = sc[0];
    }
}

// ---------------- Kernel 4: write gs (mostly zeros, sparse column e==0) ----------------
__global__ void k4_write(float4* __restrict__ out) {
    long i4 = (long)blockIdx.x * blockDim.x + threadIdx.x;
    int e4 = (int)(i4 & 15);
    long rem = i4 >> 4;
    int n = (int)(rem & (NN - 1));
    long b = rem >> 7;
    float4 v = make_float4(0.f, 0.f, 0.f, 0.f);
    if (e4 == 0 && n < EE) {
        float m = g_masked[b * EE + n];
        v.x = m * (CAPACITY / g_denom[n]);
    }
    out[i4] = v;
}

// ---------------- Kernel 5: loss ----------------
__global__ void k5_loss(float* __restrict__ lossptr) {
    double si = 0.0, si2 = 0.0, sl = 0.0, sl2 = 0.0;
    for (int n = 0; n < EE; n++) {
        double dn = (double)g_denom[n];
        double S  = dn - (double)EPS;
        double imp = (double)CAPACITY * S / dn;
        si  += imp;
        si2 += imp * imp;
        double ld = (double)g_load[n];
        sl  += ld;
        sl2 += ld * ld;
    }
    const double M = (double)(NN * EE);
    double mean_i = si / M;
    double var_i  = (si2 - si * si / M) / (M - 1.0);
    double cv_i   = var_i / (mean_i * mean_i + 1e-10);
    double mean_l = sl / M;
    double var_l  = (sl2 - sl * sl / M) / (M - 1.0);
    double cv_l   = var_l / (mean_l * mean_l + 1e-10);
    *lossptr = (float)(cv_i + cv_l);
}

extern "C" void kernel_launch(void* const* d_in, const int* in_sizes, int n_in,
                              void* d_out, int out_size) {
    const float* x    = (const float*)d_in[0];
    const float* w    = (const float*)d_in[1];
    const float* bias = (const float*)d_in[2];
    float* out = (float*)d_out;

    cudaFuncSetAttribute(k1_gemm, cudaFuncAttributeMaxDynamicSharedMemorySize, SMEM_MAX);

    k0_wsplit<<<(EE * DD) / 256, 256>>>(w);
    k1_gemm<<<ROWS / TILE_M, THREADS1, SMEM_MAX>>>(x, w, bias);
    k2_mask<<<BB / 8, 256>>>();
    k3_denom<<<EE, 256>>>();

    const long total = (long)BB * NN * EE;        // 16777216
    if ((long)out_size >= total) {
        k4_write<<<(int)(total / 4 / 256), 256>>>((float4*)out);
    }
    if ((long)out_size > total) {
        k5_loss<<<1, 1>>>(out + total);
    } else if ((long)out_size < total) {
        k5_loss<<<1, 1>>>(out);
    }
}

// round 5
// speedup vs baseline: 1.8211x; 1.6546x over previous
#include <cuda_runtime.h>
#include <cuda_bf16.h>
#include <cstdint>

// Problem constants
#define BB 2048
#define NN 128
#define DD 512
#define EE 64
#define ROWS (BB*NN)            // 262144
#define EPS 1e-6f
#define CAPACITY 2048.0f

#define TILE_M 128
#define THREADS1 288            // 9 warps: 4 A-prod, 4 B-prod, 1 MMA

// ---- tcgen05 path tiling ----
#define KC 64                   // K per chunk (64 bf16 = 128B rows, SW128)
#define NCH (DD/KC)             // 8 chunks
#define B_TILE_B (EE*128)       // 8192 per term
#define B_STAGE_B (3*B_TILE_B)  // 24576 per stage
#define NSTAGE 2
#define SMEM_TC (512 + 1024 + NSTAGE*B_STAGE_B)   // ctrl + align pad + B tiles

// TMEM columns: D0=0..63, D1=64..127, A ring at 128 (stage*96, term*32)
#define TM_D0 0
#define TM_D1 64
#define TM_A  128

// idesc: dtype=F32, atype=BF16, btype=BF16, N=64, M=128, K-major both
#define IDESC ((1u<<4)|(1u<<7)|(1u<<10)|((EE/8)<<17)|((TILE_M/16)<<24))

// Scratch (device globals; no allocation allowed)
__device__ float g_p0[ROWS];
__device__ int   g_idx[ROWS];
__device__ float g_masked[BB*EE];
__device__ float g_denom[EE];
__device__ int   g_load[EE];
__device__ __nv_bfloat16 g_wh[EE*DD];
__device__ __nv_bfloat16 g_wm[EE*DD];
__device__ __nv_bfloat16 g_wl[EE*DD];

#define HAS_TCGEN05 (defined(__CUDA_ARCH_FEAT_SM103_ALL) || defined(__CUDA_ARCH_FEAT_SM100_ALL) || defined(__CUDA_ARCH_FEAT_SM101_ALL))

// ---------------- generic helpers ----------------
__device__ __forceinline__ uint32_t sw128(uint32_t o) { return o ^ ((o >> 3) & 0x70); }

#if HAS_TCGEN05
// ---------------- tcgen05 PTX helpers (arch-specific target only) ----------------
__device__ __forceinline__ uint32_t smem_u32(const void* p) {
    uint32_t a;
    asm("{ .reg .u64 t; cvta.to.shared.u64 t, %1; cvt.u32.u64 %0, t; }"
        : "=r"(a) : "l"(p));
    return a;
}
__device__ __forceinline__ uint32_t elect1() {
    uint32_t r;
    asm volatile("{\n\t.reg .pred p;\n\telect.sync _|p, 0xFFFFFFFF;\n\t"
                 "selp.b32 %0, 1, 0, p;\n\t}" : "=r"(r));
    return r;
}
__device__ __forceinline__ uint64_t make_desc_sw128(uint32_t addr) {
    const uint64_t base = (2ull << 61) | (1ull << 46) | (64ull << 32) | (1ull << 16);
    return base | ((uint64_t)(addr >> 4) & 0x3FFF);
}
// TS-mode MMA: A in TMEM, B via SMEM descriptor
__device__ __forceinline__ void mma_ts_f16(uint32_t d, uint32_t a, uint64_t b,
                                           uint32_t idesc, uint32_t en) {
    asm volatile(
        "{\n\t.reg .pred p;\n\tsetp.ne.u32 p, %4, 0;\n\t"
        "tcgen05.mma.cta_group::1.kind::f16 [%0], [%1], %2, %3, {%5,%5,%5,%5}, p;\n\t}"
        :: "r"(d), "r"(a), "l"(b), "r"(idesc), "r"(en), "r"(0u) : "memory");
}
__device__ __forceinline__ void mbar_init(uint32_t a, uint32_t cnt) {
    asm volatile("mbarrier.init.shared.b64 [%0], %1;" :: "r"(a), "r"(cnt) : "memory");
}
__device__ __forceinline__ void mbar_arrive(uint32_t a) {
    asm volatile("mbarrier.arrive.shared.b64 _, [%0];" :: "r"(a) : "memory");
}
__device__ __forceinline__ void mbar_wait(uint32_t a, uint32_t parity) {
    uint32_t done;
    asm volatile("{\n\t.reg .pred p;\n\t"
        "mbarrier.try_wait.parity.acquire.cta.shared::cta.b64 p, [%1], %2;\n\t"
        "selp.b32 %0, 1, 0, p;\n\t}" : "=r"(done) : "r"(a), "r"(parity) : "memory");
    while (!done) {
        asm volatile("{\n\t.reg .pred p;\n\t"
            "mbarrier.try_wait.parity.acquire.cta.shared::cta.b64 p, [%1], %2, 0x989680;\n\t"
            "selp.b32 %0, 1, 0, p;\n\t}" : "=r"(done) : "r"(a), "r"(parity) : "memory");
    }
}
__device__ __forceinline__ void t5_commit(uint32_t mb) {
    asm volatile("tcgen05.commit.cta_group::1.mbarrier::arrive::one.shared::cluster.b64 [%0];"
                 :: "r"(mb) : "memory");
}
#define T5_ALLOC(smaddr, n) \
    asm volatile("tcgen05.alloc.cta_group::1.sync.aligned.shared::cta.b32 [%0], %1;" \
                 :: "r"(smaddr), "r"((uint32_t)(n)) : "memory")
#define T5_RELINQ() \
    asm volatile("tcgen05.relinquish_alloc_permit.cta_group::1.sync.aligned;")
#define T5_DEALLOC(t, n) \
    asm volatile("tcgen05.dealloc.cta_group::1.sync.aligned.b32 %0, %1;" :: "r"(t), "r"((uint32_t)(n)))
#define T5_FENCE_AFTER()  asm volatile("tcgen05.fence::after_thread_sync;" ::: "memory")
#define T5_FENCE_BEFORE() asm volatile("tcgen05.fence::before_thread_sync;" ::: "memory")
#define T5_WAIT_LD()      asm volatile("tcgen05.wait::ld.sync.aligned;" ::: "memory")
#define T5_WAIT_ST()      asm volatile("tcgen05.wait::st.sync.aligned;" ::: "memory")
#define FENCE_ASYNC()     asm volatile("fence.proxy.async.shared::cta;" ::: "memory")

#define STTM8(addr, r) \
    asm volatile("tcgen05.st.sync.aligned.32x32b.x8.b32 [%0], " \
        "{%1,%2,%3,%4,%5,%6,%7,%8};" \
        :: "r"(addr), "r"((r)[0]), "r"((r)[1]), "r"((r)[2]), "r"((r)[3]), \
           "r"((r)[4]), "r"((r)[5]), "r"((r)[6]), "r"((r)[7]) : "memory")

#define LDTM32(r, addr) \
    asm volatile( \
        "tcgen05.ld.sync.aligned.32x32b.x32.b32 " \
        "{%0, %1, %2, %3, %4, %5, %6, %7, " \
        " %8, %9, %10, %11, %12, %13, %14, %15, " \
        " %16, %17, %18, %19, %20, %21, %22, %23, " \
        " %24, %25, %26, %27, %28, %29, %30, %31}, [%32];" \
        : "=r"((r)[0]),  "=r"((r)[1]),  "=r"((r)[2]),  "=r"((r)[3]), \
          "=r"((r)[4]),  "=r"((r)[5]),  "=r"((r)[6]),  "=r"((r)[7]), \
          "=r"((r)[8]),  "=r"((r)[9]),  "=r"((r)[10]), "=r"((r)[11]), \
          "=r"((r)[12]), "=r"((r)[13]), "=r"((r)[14]), "=r"((r)[15]), \
          "=r"((r)[16]), "=r"((r)[17]), "=r"((r)[18]), "=r"((r)[19]), \
          "=r"((r)[20]), "=r"((r)[21]), "=r"((r)[22]), "=r"((r)[23]), \
          "=r"((r)[24]), "=r"((r)[25]), "=r"((r)[26]), "=r"((r)[27]), \
          "=r"((r)[28]), "=r"((r)[29]), "=r"((r)[30]), "=r"((r)[31]) \
        : "r"(addr))
#endif  // HAS_TCGEN05

// ---------------- Kernel 0: split W fp32 -> 3x bf16 ----------------
__global__ void k0_wsplit(const float* __restrict__ w) {
    int i = blockIdx.x * blockDim.x + threadIdx.x;   // 0..32767
    float v = w[i];
    __nv_bfloat16 h = __float2bfloat16(v);
    float r1 = v - __bfloat162float(h);
    __nv_bfloat16 m = __float2bfloat16(r1);
    float r2 = r1 - __bfloat162float(m);
    __nv_bfloat16 l = __float2bfloat16(r2);
    g_wh[i] = h; g_wm[i] = m; g_wl[i] = l;
}

// ---------------- Kernel 1: warp-specialized TS GEMM + softmax stats ----------------
__global__ __launch_bounds__(THREADS1, 1)
void k1_gemm(const float* __restrict__ x,
             const float* __restrict__ w,
             const float* __restrict__ bias) {
#if HAS_TCGEN05
    extern __shared__ char sm[];
    const uint32_t smem_base = smem_u32(sm);
    const uint32_t mb_f0 = smem_base + 16;   // full stage0 (256 arrivals)
    const uint32_t mb_f1 = smem_base + 24;   // full stage1
    const uint32_t mb_e0 = smem_base + 32;   // empty stage0 (commit, 1 arrival)
    const uint32_t mb_e1 = smem_base + 40;   // empty stage1
    float* bias_s = reinterpret_cast<float*>(sm + 64);
    const uint32_t tiles = (smem_base + 512 + 1023) & ~1023u;   // 1024-aligned B base
    char* tbase = sm + (tiles - smem_base);

    const int tid = threadIdx.x;
    const int wid = tid >> 5, lid = tid & 31;
    const long rowbase = (long)blockIdx.x * TILE_M;

    if (wid == 8) {
        T5_ALLOC(smem_base, 512);
        T5_RELINQ();
    }
    if (tid == 0) {
        mbar_init(mb_f0, 256); mbar_init(mb_f1, 256);
        mbar_init(mb_e0, 1);   mbar_init(mb_e1, 1);
    }
    if (tid < EE) bias_s[tid] = bias[tid];
    __syncthreads();
    const uint32_t tmem = *reinterpret_cast<uint32_t*>(sm);

    if (wid < 4) {
        // ===== A producers: 1 row/thread, convert fp32 -> 3x bf16 into TMEM =====
        const int row = tid;                       // 0..127
        const uint32_t woff = (uint32_t)wid << 21; // subpartition select
        const float4* xg = reinterpret_cast<const float4*>(x + (rowbase + row) * (size_t)DD);

        float4 f4[16];
#pragma unroll
        for (int i = 0; i < 16; i++) f4[i] = xg[i];

        int pph[2] = {1, 1};
        for (int c = 0; c < NCH; c++) {
            const int stage = c & 1;
            mbar_wait(stage ? mb_e1 : mb_e0, pph[stage]);
            pph[stage] ^= 1;

            const uint32_t acol = tmem + TM_A + stage * 96 + woff;
#pragma unroll
            for (int g = 0; g < 4; g++) {
                uint32_t h8[8], m8[8], l8[8];
#pragma unroll
                for (int i = 0; i < 4; i++) {
                    float4 v = f4[g * 4 + i];
#pragma unroll
                    for (int p = 0; p < 2; p++) {
                        float a0 = p ? v.z : v.x;
                        float a1 = p ? v.w : v.y;
                        __nv_bfloat162 H = __float22bfloat162_rn(make_float2(a0, a1));
                        float2 Hf = __bfloat1622float2(H);
                        float r0 = a0 - Hf.x, r1 = a1 - Hf.y;
                        __nv_bfloat162 M = __float22bfloat162_rn(make_float2(r0, r1));
                        float2 Mf = __bfloat1622float2(M);
                        __nv_bfloat162 L = __float22bfloat162_rn(make_float2(r0 - Mf.x, r1 - Mf.y));
                        h8[i * 2 + p] = *reinterpret_cast<uint32_t*>(&H);
                        m8[i * 2 + p] = *reinterpret_cast<uint32_t*>(&M);
                        l8[i * 2 + p] = *reinterpret_cast<uint32_t*>(&L);
                    }
                }
                STTM8(acol + g * 8,      h8);
                STTM8(acol + 32 + g * 8, m8);
                STTM8(acol + 64 + g * 8, l8);
            }
            // prefetch next chunk's x while STTM drains
            if (c + 1 < NCH) {
#pragma unroll
                for (int i = 0; i < 16; i++) f4[i] = xg[(c + 1) * 16 + i];
            }
            T5_WAIT_ST();
            T5_FENCE_BEFORE();
            mbar_arrive(stage ? mb_f1 : mb_f0);
        }

        // ===== epilogue: wait last MMAs (empty1 phase3, parity 1), read D0+D1 =====
        mbar_wait(mb_e1, 1);
        T5_FENCE_AFTER();

        float vals[EE];
        {
            uint32_t a[32], b[32];
            LDTM32(a, tmem + TM_D0);
            LDTM32(b, tmem + TM_D1);
            T5_WAIT_LD();
#pragma unroll
            for (int e = 0; e < 32; e++)
                vals[e] = __uint_as_float(a[e]) + __uint_as_float(b[e]) + bias_s[e];
            LDTM32(a, tmem + TM_D0 + 32);
            LDTM32(b, tmem + TM_D1 + 32);
            T5_WAIT_LD();
#pragma unroll
            for (int e = 0; e < 32; e++)
                vals[32 + e] = __uint_as_float(a[e]) + __uint_as_float(b[e]) + bias_s[32 + e];
        }
        T5_FENCE_BEFORE();

        float bv = vals[0];
        int be = 0;
#pragma unroll
        for (int e = 1; e < EE; e++)
            if (vals[e] > bv) { bv = vals[e]; be = e; }
        float s = 0.f;
#pragma unroll
        for (int e = 0; e < EE; e++)
            s += __expf(vals[e] - bv);

        long r = rowbase + row;
        g_p0[r]  = __expf(vals[0] - bv) / s;
        g_idx[r] = be;
    } else if (wid < 8) {
        // ===== B producers: stream W bf16 chunks into SMEM (SW128) =====
        const int bt = tid - 128;   // 0..127
        int pph[2] = {1, 1};
        for (int c = 0; c < NCH; c++) {
            const int stage = c & 1;
            mbar_wait(stage ? mb_e1 : mb_e0, pph[stage]);
            pph[stage] ^= 1;

            char* bs = tbase + stage * B_STAGE_B;
#pragma unroll
            for (int j = bt; j < 1024; j += 128) {
                int br = j >> 4, bk = j & 15;
                uint32_t sw = sw128((uint32_t)br * 128 + bk * 8);
                size_t gi = (size_t)br * DD + c * KC + bk * 4;
                *reinterpret_cast<uint2*>(bs + sw)              = *reinterpret_cast<const uint2*>(g_wh + gi);
                *reinterpret_cast<uint2*>(bs + B_TILE_B + sw)   = *reinterpret_cast<const uint2*>(g_wm + gi);
                *reinterpret_cast<uint2*>(bs + 2*B_TILE_B + sw) = *reinterpret_cast<const uint2*>(g_wl + gi);
            }
            FENCE_ASYNC();
            mbar_arrive(stage ? mb_f1 : mb_f0);
        }
    } else {
        // ===== MMA warp (warp 8) =====
        if (elect1()) {
            const int ta[6] = {0, 0, 1, 1, 0, 2};
            const int tb[6] = {0, 1, 0, 1, 2, 0};
            int cph[2] = {0, 0};
            for (int c = 0; c < NCH; c++) {
                const int stage = c & 1;
                mbar_wait(stage ? mb_f1 : mb_f0, cph[stage]);
                cph[stage] ^= 1;
                T5_FENCE_AFTER();

                uint64_t bd[3];
#pragma unroll
                for (int t = 0; t < 3; t++)
                    bd[t] = make_desc_sw128(tiles + stage * B_STAGE_B + t * B_TILE_B);
                const uint32_t abase = tmem + TM_A + stage * 96;

#pragma unroll
                for (int ks = 0; ks < 4; ks++) {
#pragma unroll
                    for (int t = 0; t < 6; t++) {
                        uint32_t d = tmem + ((t & 1) ? TM_D1 : TM_D0);
                        uint32_t a = abase + ta[t] * 32 + ks * 8;
                        uint64_t b = bd[tb[t]] + ks * 2;
                        uint32_t en = !(c == 0 && ks == 0 && t < 2);
                        mma_ts_f16(d, a, b, IDESC, en);
                    }
                }
                t5_commit(stage ? mb_e1 : mb_e0);
            }
        }
    }

    __syncthreads();
    if (wid == 8) {
        T5_DEALLOC(tmem, 512);
    }
#else
    // ---------------- portable fallback (generic-PTX compile phase only) ----------------
    const int tid = threadIdx.x;
    const long rowbase = (long)blockIdx.x * TILE_M;
    if (tid < TILE_M) {
        const float* xr = x + (rowbase + tid) * (size_t)DD;
        float bv = -1e30f;
        int be = 0;
        float vals[EE];
        for (int e = 0; e < EE; e++) {
            float acc = 0.f;
            const float* wr = w + (size_t)e * DD;
            for (int k = 0; k < DD; k++) acc = fmaf(xr[k], wr[k], acc);
            acc += bias[e];
            vals[e] = acc;
            if (acc > bv) { bv = acc; be = e; }
        }
        float s = 0.f;
        for (int e = 0; e < EE; e++) s += __expf(vals[e] - bv);
        long r = rowbase + tid;
        g_p0[r]  = __expf(vals[0] - bv) / s;
        g_idx[r] = be;
    }
#endif
}

// ---------------- Kernel 2: per-batch membership mask -> masked p0 ----------------
__global__ void k2_mask(void) {
    int b    = blockIdx.x * 8 + (threadIdx.x >> 5);
    int lane = threadIdx.x & 31;
    long base = (long)b * NN;
    unsigned long long m = 0ull;
#pragma unroll
    for (int q = 0; q < 4; q++) {
        int v = g_idx[base + lane + 32 * q];
        m |= 1ull << v;
    }
#pragma unroll
    for (int off = 16; off >= 1; off >>= 1)
        m |= __shfl_xor_sync(0xffffffffu, m, off);
#pragma unroll
    for (int h = 0; h < 2; h++) {
        int n = lane + 32 * h;
        g_masked[b * EE + n] = ((m >> n) & 1ull) ? g_p0[base + n] : 0.f;
    }
}

// ---------------- Kernel 3: deterministic column sums (denom, load) ----------------
__global__ void k3_denom(void) {
    __shared__ float sv[256];
    __shared__ int   sc[256];
    int n = blockIdx.x;
    int t = threadIdx.x;
    float s = 0.f;
    int cnt = 0;
    for (int k = 0; k < BB / 256; k++) {
        float v = g_masked[(size_t)(t + k * 256) * EE + n];
        s += v;
        cnt += (v > 0.f);
    }
    sv[t] = s; sc[t] = cnt;
    __syncthreads();
    for (int off = 128; off >= 1; off >>= 1) {
        if (t < off) { sv[t] += sv[t + off]; sc[t] += sc[t + off]; }
        __syncthreads();
    }
    if (t == 0) {
        g_denom[n] = sv[0] + EPS;
        g_load[n]  = sc[0];
    }
}

// ---------------- Kernel 4: write gs (mostly zeros, sparse column e==0) ----------------
__global__ void k4_write(float4* __restrict__ out) {
    long i4 = (long)blockIdx.x * blockDim.x + threadIdx.x;
    int e4 = (int)(i4 & 15);
    long rem = i4 >> 4;
    int n = (int)(rem & (NN - 1));
    long b = rem >> 7;
    float4 v = make_float4(0.f, 0.f, 0.f, 0.f);
    if (e4 == 0 && n < EE) {
        float m = g_masked[b * EE + n];
        v.x = m * (CAPACITY / g_denom[n]);
    }
    out[i4] = v;
}

// ---------------- Kernel 5: loss ----------------
__global__ void k5_loss(float* __restrict__ lossptr) {
    double si = 0.0, si2 = 0.0, sl = 0.0, sl2 = 0.0;
    for (int n = 0; n < EE; n++) {
        double dn = (double)g_denom[n];
        double S  = dn - (double)EPS;
        double imp = (double)CAPACITY * S / dn;
        si  += imp;
        si2 += imp * imp;
        double ld = (double)g_load[n];
        sl  += ld;
        sl2 += ld * ld;
    }
    const double M = (double)(NN * EE);
    double mean_i = si / M;
    double var_i  = (si2 - si * si / M) / (M - 1.0);
    double cv_i   = var_i / (mean_i * mean_i + 1e-10);
    double mean_l = sl / M;
    double var_l  = (sl2 - sl * sl / M) / (M - 1.0);
    double cv_l   = var_l / (mean_l * mean_l + 1e-10);
    *lossptr = (float)(cv_i + cv_l);
}

extern "C" void kernel_launch(void* const* d_in, const int* in_sizes, int n_in,
                              void* d_out, int out_size) {
    const float* x    = (const float*)d_in[0];
    const float* w    = (const float*)d_in[1];
    const float* bias = (const float*)d_in[2];
    float* out = (float*)d_out;

    cudaFuncSetAttribute(k1_gemm, cudaFuncAttributeMaxDynamicSharedMemorySize, SMEM_TC);

    k0_wsplit<<<(EE * DD) / 256, 256>>>(w);
    k1_gemm<<<ROWS / TILE_M, THREADS1, SMEM_TC>>>(x, w, bias);
    k2_mask<<<BB / 8, 256>>>();
    k3_denom<<<EE, 256>>>();

    const long total = (long)BB * NN * EE;        // 16777216
    if ((long)out_size >= total) {
        k4_write<<<(int)(total / 4 / 256), 256>>>((float4*)out);
    }
    if ((long)out_size > total) {
        k5_loss<<<1, 1>>>(out + total);
    } else if ((long)out_size < total) {
        k5_loss<<<1, 1>>>(out);
    }
}

// round 6
// speedup vs baseline: 2.1049x; 1.1558x over previous
#include <cuda_runtime.h>
#include <cuda_bf16.h>
#include <cstdint>

// Problem constants
#define BB 2048
#define NN 128
#define DD 512
#define EE 64
#define ROWS (BB*NN)            // 262144
#define EPS 1e-6f
#define CAPACITY 2048.0f

#define TILE_M 128
#define THREADS1 416            // 13 warps: 8 A-prod, 4 B-prod, 1 MMA

// ---- tcgen05 path tiling ----
#define KC 64                   // K per chunk (64 bf16 = 128B rows, SW128)
#define NCH (DD/KC)             // 8 chunks
#define B_TILE_B (EE*128)       // 8192 per term
#define B_STAGE_B (3*B_TILE_B)  // 24576 per stage
#define NSTAGE 2
#define SMEM_TC (512 + 1024 + NSTAGE*B_STAGE_B)

// TMEM columns: D=0..63, A ring at 64 (stage*96, term*32) -> alloc 256
#define TM_D 0
#define TM_A 64
#define TMEM_COLS 256

// idesc: dtype=F32, atype=BF16, btype=BF16, N=64, M=128, K-major both
#define IDESC ((1u<<4)|(1u<<7)|(1u<<10)|((EE/8)<<17)|((TILE_M/16)<<24))

// Scratch (device globals; no allocation allowed)
__device__ float g_p0[ROWS];
__device__ int   g_idx[ROWS];
__device__ float g_masked[BB*EE];
__device__ float g_denom[EE];
__device__ int   g_load[EE];
__device__ __nv_bfloat16 g_wh[EE*DD];
__device__ __nv_bfloat16 g_wm[EE*DD];
__device__ __nv_bfloat16 g_wl[EE*DD];

#define HAS_TCGEN05 (defined(__CUDA_ARCH_FEAT_SM103_ALL) || defined(__CUDA_ARCH_FEAT_SM100_ALL) || defined(__CUDA_ARCH_FEAT_SM101_ALL))

// ---------------- generic helpers ----------------
__device__ __forceinline__ uint32_t sw128(uint32_t o) { return o ^ ((o >> 3) & 0x70); }

#if HAS_TCGEN05
// ---------------- tcgen05 PTX helpers (arch-specific target only) ----------------
__device__ __forceinline__ uint32_t smem_u32(const void* p) {
    uint32_t a;
    asm("{ .reg .u64 t; cvta.to.shared.u64 t, %1; cvt.u32.u64 %0, t; }"
        : "=r"(a) : "l"(p));
    return a;
}
__device__ __forceinline__ uint32_t elect1() {
    uint32_t r;
    asm volatile("{\n\t.reg .pred p;\n\telect.sync _|p, 0xFFFFFFFF;\n\t"
                 "selp.b32 %0, 1, 0, p;\n\t}" : "=r"(r));
    return r;
}
__device__ __forceinline__ uint64_t make_desc_sw128(uint32_t addr) {
    const uint64_t base = (2ull << 61) | (1ull << 46) | (64ull << 32) | (1ull << 16);
    return base | ((uint64_t)(addr >> 4) & 0x3FFF);
}
// TS-mode MMA: A in TMEM, B via SMEM descriptor
__device__ __forceinline__ void mma_ts_f16(uint32_t d, uint32_t a, uint64_t b,
                                           uint32_t idesc, uint32_t en) {
    asm volatile(
        "{\n\t.reg .pred p;\n\tsetp.ne.u32 p, %4, 0;\n\t"
        "tcgen05.mma.cta_group::1.kind::f16 [%0], [%1], %2, %3, {%5,%5,%5,%5}, p;\n\t}"
        :: "r"(d), "r"(a), "l"(b), "r"(idesc), "r"(en), "r"(0u) : "memory");
}
__device__ __forceinline__ void mbar_init(uint32_t a, uint32_t cnt) {
    asm volatile("mbarrier.init.shared.b64 [%0], %1;" :: "r"(a), "r"(cnt) : "memory");
}
__device__ __forceinline__ void mbar_arrive(uint32_t a) {
    asm volatile("mbarrier.arrive.shared.b64 _, [%0];" :: "r"(a) : "memory");
}
__device__ __forceinline__ void mbar_wait(uint32_t a, uint32_t parity) {
    uint32_t done;
    asm volatile("{\n\t.reg .pred p;\n\t"
        "mbarrier.try_wait.parity.acquire.cta.shared::cta.b64 p, [%1], %2;\n\t"
        "selp.b32 %0, 1, 0, p;\n\t}" : "=r"(done) : "r"(a), "r"(parity) : "memory");
    while (!done) {
        asm volatile("{\n\t.reg .pred p;\n\t"
            "mbarrier.try_wait.parity.acquire.cta.shared::cta.b64 p, [%1], %2, 0x989680;\n\t"
            "selp.b32 %0, 1, 0, p;\n\t}" : "=r"(done) : "r"(a), "r"(parity) : "memory");
    }
}
__device__ __forceinline__ void t5_commit(uint32_t mb) {
    asm volatile("tcgen05.commit.cta_group::1.mbarrier::arrive::one.shared::cluster.b64 [%0];"
                 :: "r"(mb) : "memory");
}
#define T5_ALLOC(smaddr, n) \
    asm volatile("tcgen05.alloc.cta_group::1.sync.aligned.shared::cta.b32 [%0], %1;" \
                 :: "r"(smaddr), "r"((uint32_t)(n)) : "memory")
#define T5_RELINQ() \
    asm volatile("tcgen05.relinquish_alloc_permit.cta_group::1.sync.aligned;")
#define T5_DEALLOC(t, n) \
    asm volatile("tcgen05.dealloc.cta_group::1.sync.aligned.b32 %0, %1;" :: "r"(t), "r"((uint32_t)(n)))
#define T5_FENCE_AFTER()  asm volatile("tcgen05.fence::after_thread_sync;" ::: "memory")
#define T5_FENCE_BEFORE() asm volatile("tcgen05.fence::before_thread_sync;" ::: "memory")
#define T5_WAIT_LD()      asm volatile("tcgen05.wait::ld.sync.aligned;" ::: "memory")
#define T5_WAIT_ST()      asm volatile("tcgen05.wait::st.sync.aligned;" ::: "memory")
#define FENCE_ASYNC()     asm volatile("fence.proxy.async.shared::cta;" ::: "memory")

#define STTM8(addr, r) \
    asm volatile("tcgen05.st.sync.aligned.32x32b.x8.b32 [%0], " \
        "{%1,%2,%3,%4,%5,%6,%7,%8};" \
        :: "r"(addr), "r"((r)[0]), "r"((r)[1]), "r"((r)[2]), "r"((r)[3]), \
           "r"((r)[4]), "r"((r)[5]), "r"((r)[6]), "r"((r)[7]) : "memory")

#define LDTM32(r, addr) \
    asm volatile( \
        "tcgen05.ld.sync.aligned.32x32b.x32.b32 " \
        "{%0, %1, %2, %3, %4, %5, %6, %7, " \
        " %8, %9, %10, %11, %12, %13, %14, %15, " \
        " %16, %17, %18, %19, %20, %21, %22, %23, " \
        " %24, %25, %26, %27, %28, %29, %30, %31}, [%32];" \
        : "=r"((r)[0]),  "=r"((r)[1]),  "=r"((r)[2]),  "=r"((r)[3]), \
          "=r"((r)[4]),  "=r"((r)[5]),  "=r"((r)[6]),  "=r"((r)[7]), \
          "=r"((r)[8]),  "=r"((r)[9]),  "=r"((r)[10]), "=r"((r)[11]), \
          "=r"((r)[12]), "=r"((r)[13]), "=r"((r)[14]), "=r"((r)[15]), \
          "=r"((r)[16]), "=r"((r)[17]), "=r"((r)[18]), "=r"((r)[19]), \
          "=r"((r)[20]), "=r"((r)[21]), "=r"((r)[22]), "=r"((r)[23]), \
          "=r"((r)[24]), "=r"((r)[25]), "=r"((r)[26]), "=r"((r)[27]), \
          "=r"((r)[28]), "=r"((r)[29]), "=r"((r)[30]), "=r"((r)[31]) \
        : "r"(addr))
#endif  // HAS_TCGEN05

// ---------------- Kernel 0: split W fp32 -> 3x bf16 ----------------
__global__ void k0_wsplit(const float* __restrict__ w) {
    int i = blockIdx.x * blockDim.x + threadIdx.x;   // 0..32767
    float v = w[i];
    __nv_bfloat16 h = __float2bfloat16(v);
    float r1 = v - __bfloat162float(h);
    __nv_bfloat16 m = __float2bfloat16(r1);
    float r2 = r1 - __bfloat162float(m);
    __nv_bfloat16 l = __float2bfloat16(r2);
    g_wh[i] = h; g_wm[i] = m; g_wl[i] = l;
}

// ---------------- Kernel 1: warp-specialized TS GEMM + softmax stats ----------------
__global__ __launch_bounds__(THREADS1, 2)
void k1_gemm(const float* __restrict__ x,
             const float* __restrict__ w,
             const float* __restrict__ bias) {
#if HAS_TCGEN05
    extern __shared__ char sm[];
    const uint32_t smem_base = smem_u32(sm);
    const uint32_t mb_f0 = smem_base + 16;   // full stage0 (384 arrivals)
    const uint32_t mb_f1 = smem_base + 24;   // full stage1
    const uint32_t mb_e0 = smem_base + 32;   // empty stage0 (commit, 1 arrival)
    const uint32_t mb_e1 = smem_base + 40;   // empty stage1
    float* bias_s = reinterpret_cast<float*>(sm + 64);
    const uint32_t tiles = (smem_base + 512 + 1023) & ~1023u;   // 1024-aligned B base
    char* tbase = sm + (tiles - smem_base);

    const int tid = threadIdx.x;
    const int wid = tid >> 5, lid = tid & 31;
    const long rowbase = (long)blockIdx.x * TILE_M;

    if (wid == 12) {
        T5_ALLOC(smem_base, TMEM_COLS);
        T5_RELINQ();
    }
    if (tid == 0) {
        mbar_init(mb_f0, 384); mbar_init(mb_f1, 384);
        mbar_init(mb_e0, 1);   mbar_init(mb_e1, 1);
    }
    if (tid < EE) bias_s[tid] = bias[tid];
    __syncthreads();
    const uint32_t tmem = *reinterpret_cast<uint32_t*>(sm);

    if (wid < 8) {
        // ===== A producers: 2 threads/row (8 warps), convert fp32 -> 3x bf16 -> TMEM =====
        const int awid  = wid & 3;              // subpartition
        const int khalf = wid >> 2;             // which 32-k half of the chunk
        const int row   = awid * 32 + lid;
        const uint32_t woff = (uint32_t)awid << 21;
        const uint32_t ccol = (uint32_t)khalf * 16;   // col offset within 32-col term
        const float4* xg = reinterpret_cast<const float4*>(x) +
                           (size_t)(rowbase + row) * (DD / 4) + khalf * 8;

        int pph[2] = {1, 1};
        for (int c = 0; c < NCH; c++) {
            // issue x loads BEFORE the empty wait (latency hidden by wait)
            float4 f4[8];
#pragma unroll
            for (int i = 0; i < 8; i++) f4[i] = xg[c * 16 + i];

            const int stage = c & 1;
            mbar_wait(stage ? mb_e1 : mb_e0, pph[stage]);
            pph[stage] ^= 1;

            const uint32_t acol = tmem + TM_A + stage * 96 + woff + ccol;
#pragma unroll
            for (int g = 0; g < 2; g++) {
                uint32_t h8[8], m8[8], l8[8];
#pragma unroll
                for (int i = 0; i < 4; i++) {
                    float4 v = f4[g * 4 + i];
#pragma unroll
                    for (int p = 0; p < 2; p++) {
                        float a0 = p ? v.z : v.x;
                        float a1 = p ? v.w : v.y;
                        __nv_bfloat162 H = __float22bfloat162_rn(make_float2(a0, a1));
                        float2 Hf = __bfloat1622float2(H);
                        float r0 = a0 - Hf.x, r1 = a1 - Hf.y;
                        __nv_bfloat162 M = __float22bfloat162_rn(make_float2(r0, r1));
                        float2 Mf = __bfloat1622float2(M);
                        __nv_bfloat162 L = __float22bfloat162_rn(make_float2(r0 - Mf.x, r1 - Mf.y));
                        h8[i * 2 + p] = *reinterpret_cast<uint32_t*>(&H);
                        m8[i * 2 + p] = *reinterpret_cast<uint32_t*>(&M);
                        l8[i * 2 + p] = *reinterpret_cast<uint32_t*>(&L);
                    }
                }
                STTM8(acol + 0 * 32 + g * 8, h8);
                STTM8(acol + 1 * 32 + g * 8, m8);
                STTM8(acol + 2 * 32 + g * 8, l8);
            }
            T5_WAIT_ST();
            T5_FENCE_BEFORE();
            mbar_arrive(stage ? mb_f1 : mb_f0);
        }

        // ===== epilogue (warps 0-3 only): wait last commit, read D, softmax =====
        if (wid < 4) {
            mbar_wait(mb_e1, 1);
            T5_FENCE_AFTER();

            float vals[EE];
            {
                uint32_t a[32];
                LDTM32(a, tmem + TM_D);
                T5_WAIT_LD();
#pragma unroll
                for (int e = 0; e < 32; e++)
                    vals[e] = __uint_as_float(a[e]) + bias_s[e];
                LDTM32(a, tmem + TM_D + 32);
                T5_WAIT_LD();
#pragma unroll
                for (int e = 0; e < 32; e++)
                    vals[32 + e] = __uint_as_float(a[e]) + bias_s[32 + e];
            }
            T5_FENCE_BEFORE();

            float bv = vals[0];
            int be = 0;
#pragma unroll
            for (int e = 1; e < EE; e++)
                if (vals[e] > bv) { bv = vals[e]; be = e; }
            float s = 0.f;
#pragma unroll
            for (int e = 0; e < EE; e++)
                s += __expf(vals[e] - bv);

            long r = rowbase + wid * 32 + lid;
            g_p0[r]  = __expf(vals[0] - bv) / s;
            g_idx[r] = be;
        }
    } else if (wid < 12) {
        // ===== B producers: stream W bf16 chunks into SMEM (SW128) =====
        const int bt = tid - 256;   // 0..127
        int pph[2] = {1, 1};
        for (int c = 0; c < NCH; c++) {
            const int stage = c & 1;
            mbar_wait(stage ? mb_e1 : mb_e0, pph[stage]);
            pph[stage] ^= 1;

            char* bs = tbase + stage * B_STAGE_B;
#pragma unroll
            for (int j = bt; j < 1024; j += 128) {
                int br = j >> 4, bk = j & 15;
                uint32_t sw = sw128((uint32_t)br * 128 + bk * 8);
                size_t gi = (size_t)br * DD + c * KC + bk * 4;
                *reinterpret_cast<uint2*>(bs + sw)              = *reinterpret_cast<const uint2*>(g_wh + gi);
                *reinterpret_cast<uint2*>(bs + B_TILE_B + sw)   = *reinterpret_cast<const uint2*>(g_wm + gi);
                *reinterpret_cast<uint2*>(bs + 2*B_TILE_B + sw) = *reinterpret_cast<const uint2*>(g_wl + gi);
            }
            FENCE_ASYNC();
            mbar_arrive(stage ? mb_f1 : mb_f0);
        }
    } else {
        // ===== MMA warp (warp 12) =====
        if (elect1()) {
            const int ta[6] = {0, 0, 1, 1, 0, 2};
            const int tb[6] = {0, 1, 0, 1, 2, 0};
            int cph[2] = {0, 0};
            for (int c = 0; c < NCH; c++) {
                const int stage = c & 1;
                mbar_wait(stage ? mb_f1 : mb_f0, cph[stage]);
                cph[stage] ^= 1;
                T5_FENCE_AFTER();

                uint64_t bd[3];
#pragma unroll
                for (int t = 0; t < 3; t++)
                    bd[t] = make_desc_sw128(tiles + stage * B_STAGE_B + t * B_TILE_B);
                const uint32_t abase = tmem + TM_A + stage * 96;

#pragma unroll
                for (int ks = 0; ks < 4; ks++) {
#pragma unroll
                    for (int t = 0; t < 6; t++) {
                        uint32_t a = abase + ta[t] * 32 + ks * 8;
                        uint64_t b = bd[tb[t]] + ks * 2;
                        uint32_t en = !(c == 0 && ks == 0 && t == 0);
                        mma_ts_f16(tmem + TM_D, a, b, IDESC, en);
                    }
                }
                t5_commit(stage ? mb_e1 : mb_e0);
            }
        }
    }

    __syncthreads();
    if (wid == 12) {
        T5_DEALLOC(tmem, TMEM_COLS);
    }
#else
    // ---------------- portable fallback (generic-PTX compile phase only) ----------------
    const int tid = threadIdx.x;
    const long rowbase = (long)blockIdx.x * TILE_M;
    if (tid < TILE_M) {
        const float* xr = x + (rowbase + tid) * (size_t)DD;
        float bv = -1e30f;
        int be = 0;
        float vals[EE];
        for (int e = 0; e < EE; e++) {
            float acc = 0.f;
            const float* wr = w + (size_t)e * DD;
            for (int k = 0; k < DD; k++) acc = fmaf(xr[k], wr[k], acc);
            acc += bias[e];
            vals[e] = acc;
            if (acc > bv) { bv = acc; be = e; }
        }
        float s = 0.f;
        for (int e = 0; e < EE; e++) s += __expf(vals[e] - bv);
        long r = rowbase + tid;
        g_p0[r]  = __expf(vals[0] - bv) / s;
        g_idx[r] = be;
    }
#endif
}

// ---------------- Kernel 2: per-batch membership mask -> masked p0 ----------------
__global__ void k2_mask(void) {
    int b    = blockIdx.x * 8 + (threadIdx.x >> 5);
    int lane = threadIdx.x & 31;
    long base = (long)b * NN;
    unsigned long long m = 0ull;
#pragma unroll
    for (int q = 0; q < 4; q++) {
        int v = g_idx[base + lane + 32 * q];
        m |= 1ull << v;
    }
#pragma unroll
    for (int off = 16; off >= 1; off >>= 1)
        m |= __shfl_xor_sync(0xffffffffu, m, off);
#pragma unroll
    for (int h = 0; h < 2; h++) {
        int n = lane + 32 * h;
        g_masked[b * EE + n] = ((m >> n) & 1ull) ? g_p0[base + n] : 0.f;
    }
}

// ---------------- Kernel 3: deterministic column sums (denom, load) ----------------
__global__ void k3_denom(void) {
    __shared__ float sv[256];
    __shared__ int   sc[256];
    int n = blockIdx.x;
    int t = threadIdx.x;
    float s = 0.f;
    int cnt = 0;
    for (int k = 0; k < BB / 256; k++) {
        float v = g_masked[(size_t)(t + k * 256) * EE + n];
        s += v;
        cnt += (v > 0.f);
    }
    sv[t] = s; sc[t] = cnt;
    __syncthreads();
    for (int off = 128; off >= 1; off >>= 1) {
        if (t < off) { sv[t] += sv[t + off]; sc[t] += sc[t + off]; }
        __syncthreads();
    }
    if (t == 0) {
        g_denom[n] = sv[0] + EPS;
        g_load[n]  = sc[0];
    }
}

// ---------------- Kernel 4: write gs (mostly zeros, sparse column e==0) ----------------
__global__ void k4_write(float4* __restrict__ out) {
    long i4 = (long)blockIdx.x * blockDim.x + threadIdx.x;
    int e4 = (int)(i4 & 15);
    long rem = i4 >> 4;
    int n = (int)(rem & (NN - 1));
    long b = rem >> 7;
    float4 v = make_float4(0.f, 0.f, 0.f, 0.f);
    if (e4 == 0 && n < EE) {
        float m = g_masked[b * EE + n];
        v.x = m * (CAPACITY / g_denom[n]);
    }
    out[i4] = v;
}

// ---------------- Kernel 5: loss ----------------
__global__ void k5_loss(float* __restrict__ lossptr) {
    double si = 0.0, si2 = 0.0, sl = 0.0, sl2 = 0.0;
    for (int n = 0; n < EE; n++) {
        double dn = (double)g_denom[n];
        double S  = dn - (double)EPS;
        double imp = (double)CAPACITY * S / dn;
        si  += imp;
        si2 += imp * imp;
        double ld = (double)g_load[n];
        sl  += ld;
        sl2 += ld * ld;
    }
    const double M = (double)(NN * EE);
    double mean_i = si / M;
    double var_i  = (si2 - si * si / M) / (M - 1.0);
    double cv_i   = var_i / (mean_i * mean_i + 1e-10);
    double mean_l = sl / M;
    double var_l  = (sl2 - sl * sl / M) / (M - 1.0);
    double cv_l   = var_l / (mean_l * mean_l + 1e-10);
    *lossptr = (float)(cv_i + cv_l);
}

extern "C" void kernel_launch(void* const* d_in, const int* in_sizes, int n_in,
                              void* d_out, int out_size) {
    const float* x    = (const float*)d_in[0];
    const float* w    = (const float*)d_in[1];
    const float* bias = (const float*)d_in[2];
    float* out = (float*)d_out;

    cudaFuncSetAttribute(k1_gemm, cudaFuncAttributeMaxDynamicSharedMemorySize, SMEM_TC);

    k0_wsplit<<<(EE * DD) / 256, 256>>>(w);
    k1_gemm<<<ROWS / TILE_M, THREADS1, SMEM_TC>>>(x, w, bias);
    k2_mask<<<BB / 8, 256>>>();
    k3_denom<<<EE, 256>>>();

    const long total = (long)BB * NN * EE;        // 16777216
    if ((long)out_size >= total) {
        k4_write<<<(int)(total / 4 / 256), 256>>>((float4*)out);
    }
    if ((long)out_size > total) {
        k5_loss<<<1, 1>>>(out + total);
    } else if ((long)out_size < total) {
        k5_loss<<<1, 1>>>(out);
    }
}

// round 7
// speedup vs baseline: 2.2232x; 1.0562x over previous
#include <cuda_runtime.h>
#include <cuda_bf16.h>
#include <cstdint>

// Problem constants
#define BB 2048
#define NN 128
#define DD 512
#define EE 64
#define ROWS (BB*NN)            // 262144
#define EPS 1e-6f
#define CAPACITY 2048.0f

#define TILE_M 128
#define THREADS1 416            // 13 warps: 8 A-prod, 4 B-prod, 1 MMA

// ---- tcgen05 path tiling ----
#define KC 64                   // K per chunk (64 bf16 = 128B rows, SW128)
#define NCH (DD/KC)             // 8 chunks
#define B_TILE_B (EE*128)       // 8192 per term
#define B_STAGE_B (3*B_TILE_B)  // 24576 per stage
#define NSTAGE 2
#define SMEM_TC (512 + 1024 + NSTAGE*B_STAGE_B)

// TMEM columns: D=0..63, A ring at 64 (stage*96, term*32) -> alloc 256
#define TM_D 0
#define TM_A 64
#define TMEM_COLS 256

// idesc: dtype=F32, atype=BF16, btype=BF16, N=64, M=128, K-major both
#define IDESC ((1u<<4)|(1u<<7)|(1u<<10)|((EE/8)<<17)|((TILE_M/16)<<24))

// Scratch (device globals; no allocation allowed)
__device__ float g_p0[ROWS];
__device__ int   g_idx[ROWS];
__device__ float g_masked[BB*EE];
__device__ float g_denom[EE];
__device__ int   g_load[EE];
__device__ __align__(16) __nv_bfloat16 g_wh[EE*DD];
__device__ __align__(16) __nv_bfloat16 g_wm[EE*DD];
__device__ __align__(16) __nv_bfloat16 g_wl[EE*DD];

#define HAS_TCGEN05 (defined(__CUDA_ARCH_FEAT_SM103_ALL) || defined(__CUDA_ARCH_FEAT_SM100_ALL) || defined(__CUDA_ARCH_FEAT_SM101_ALL))

// ---------------- generic helpers ----------------
__device__ __forceinline__ uint32_t sw128(uint32_t o) { return o ^ ((o >> 3) & 0x70); }

#if HAS_TCGEN05
// ---------------- tcgen05 PTX helpers (arch-specific target only) ----------------
__device__ __forceinline__ uint32_t smem_u32(const void* p) {
    uint32_t a;
    asm("{ .reg .u64 t; cvta.to.shared.u64 t, %1; cvt.u32.u64 %0, t; }"
        : "=r"(a) : "l"(p));
    return a;
}
__device__ __forceinline__ uint32_t elect1() {
    uint32_t r;
    asm volatile("{\n\t.reg .pred p;\n\telect.sync _|p, 0xFFFFFFFF;\n\t"
                 "selp.b32 %0, 1, 0, p;\n\t}" : "=r"(r));
    return r;
}
__device__ __forceinline__ uint64_t make_desc_sw128(uint32_t addr) {
    const uint64_t base = (2ull << 61) | (1ull << 46) | (64ull << 32) | (1ull << 16);
    return base | ((uint64_t)(addr >> 4) & 0x3FFF);
}
// TS-mode MMA: A in TMEM, B via SMEM descriptor
__device__ __forceinline__ void mma_ts_f16(uint32_t d, uint32_t a, uint64_t b,
                                           uint32_t idesc, uint32_t en) {
    asm volatile(
        "{\n\t.reg .pred p;\n\tsetp.ne.u32 p, %4, 0;\n\t"
        "tcgen05.mma.cta_group::1.kind::f16 [%0], [%1], %2, %3, {%5,%5,%5,%5}, p;\n\t}"
        :: "r"(d), "r"(a), "l"(b), "r"(idesc), "r"(en), "r"(0u) : "memory");
}
__device__ __forceinline__ void mbar_init(uint32_t a, uint32_t cnt) {
    asm volatile("mbarrier.init.shared.b64 [%0], %1;" :: "r"(a), "r"(cnt) : "memory");
}
__device__ __forceinline__ void mbar_arrive(uint32_t a) {
    asm volatile("mbarrier.arrive.shared.b64 _, [%0];" :: "r"(a) : "memory");
}
__device__ __forceinline__ void mbar_wait(uint32_t a, uint32_t parity) {
    uint32_t done;
    asm volatile("{\n\t.reg .pred p;\n\t"
        "mbarrier.try_wait.parity.acquire.cta.shared::cta.b64 p, [%1], %2;\n\t"
        "selp.b32 %0, 1, 0, p;\n\t}" : "=r"(done) : "r"(a), "r"(parity) : "memory");
    while (!done) {
        asm volatile("{\n\t.reg .pred p;\n\t"
            "mbarrier.try_wait.parity.acquire.cta.shared::cta.b64 p, [%1], %2, 0x989680;\n\t"
            "selp.b32 %0, 1, 0, p;\n\t}" : "=r"(done) : "r"(a), "r"(parity) : "memory");
    }
}
__device__ __forceinline__ void t5_commit(uint32_t mb) {
    asm volatile("tcgen05.commit.cta_group::1.mbarrier::arrive::one.shared::cluster.b64 [%0];"
                 :: "r"(mb) : "memory");
}
#define T5_ALLOC(smaddr, n) \
    asm volatile("tcgen05.alloc.cta_group::1.sync.aligned.shared::cta.b32 [%0], %1;" \
                 :: "r"(smaddr), "r"((uint32_t)(n)) : "memory")
#define T5_RELINQ() \
    asm volatile("tcgen05.relinquish_alloc_permit.cta_group::1.sync.aligned;")
#define T5_DEALLOC(t, n) \
    asm volatile("tcgen05.dealloc.cta_group::1.sync.aligned.b32 %0, %1;" :: "r"(t), "r"((uint32_t)(n)))
#define T5_FENCE_AFTER()  asm volatile("tcgen05.fence::after_thread_sync;" ::: "memory")
#define T5_FENCE_BEFORE() asm volatile("tcgen05.fence::before_thread_sync;" ::: "memory")
#define T5_WAIT_LD()      asm volatile("tcgen05.wait::ld.sync.aligned;" ::: "memory")
#define T5_WAIT_ST()      asm volatile("tcgen05.wait::st.sync.aligned;" ::: "memory")
#define FENCE_ASYNC()     asm volatile("fence.proxy.async.shared::cta;" ::: "memory")

#define STTM8(addr, r) \
    asm volatile("tcgen05.st.sync.aligned.32x32b.x8.b32 [%0], " \
        "{%1,%2,%3,%4,%5,%6,%7,%8};" \
        :: "r"(addr), "r"((r)[0]), "r"((r)[1]), "r"((r)[2]), "r"((r)[3]), \
           "r"((r)[4]), "r"((r)[5]), "r"((r)[6]), "r"((r)[7]) : "memory")

#define LDTM32(r, addr) \
    asm volatile( \
        "tcgen05.ld.sync.aligned.32x32b.x32.b32 " \
        "{%0, %1, %2, %3, %4, %5, %6, %7, " \
        " %8, %9, %10, %11, %12, %13, %14, %15, " \
        " %16, %17, %18, %19, %20, %21, %22, %23, " \
        " %24, %25, %26, %27, %28, %29, %30, %31}, [%32];" \
        : "=r"((r)[0]),  "=r"((r)[1]),  "=r"((r)[2]),  "=r"((r)[3]), \
          "=r"((r)[4]),  "=r"((r)[5]),  "=r"((r)[6]),  "=r"((r)[7]), \
          "=r"((r)[8]),  "=r"((r)[9]),  "=r"((r)[10]), "=r"((r)[11]), \
          "=r"((r)[12]), "=r"((r)[13]), "=r"((r)[14]), "=r"((r)[15]), \
          "=r"((r)[16]), "=r"((r)[17]), "=r"((r)[18]), "=r"((r)[19]), \
          "=r"((r)[20]), "=r"((r)[21]), "=r"((r)[22]), "=r"((r)[23]), \
          "=r"((r)[24]), "=r"((r)[25]), "=r"((r)[26]), "=r"((r)[27]), \
          "=r"((r)[28]), "=r"((r)[29]), "=r"((r)[30]), "=r"((r)[31]) \
        : "r"(addr))
#endif  // HAS_TCGEN05

// ---------------- Kernel 0 (split into 3 launches so k1 is the 4th launch) ----------------
__global__ void k0h(const float* __restrict__ w) {
    int i = blockIdx.x * blockDim.x + threadIdx.x;
    g_wh[i] = __float2bfloat16(w[i]);
}
__global__ void k0m(const float* __restrict__ w) {
    int i = blockIdx.x * blockDim.x + threadIdx.x;
    float v = w[i];
    float r1 = v - __bfloat162float(__float2bfloat16(v));
    g_wm[i] = __float2bfloat16(r1);
}
__global__ void k0l(const float* __restrict__ w) {
    int i = blockIdx.x * blockDim.x + threadIdx.x;
    float v = w[i];
    float r1 = v - __bfloat162float(__float2bfloat16(v));
    float r2 = r1 - __bfloat162float(__float2bfloat16(r1));
    g_wl[i] = __float2bfloat16(r2);
}

// ---------------- Kernel 1: warp-specialized TS GEMM + softmax stats ----------------
__global__ __launch_bounds__(THREADS1, 2)
void k1_gemm(const float* __restrict__ x,
             const float* __restrict__ w,
             const float* __restrict__ bias) {
#if HAS_TCGEN05
    extern __shared__ char sm[];
    const uint32_t smem_base = smem_u32(sm);
    const uint32_t mb_f0 = smem_base + 16;   // full stage0 (384 arrivals)
    const uint32_t mb_f1 = smem_base + 24;   // full stage1
    const uint32_t mb_e0 = smem_base + 32;   // empty stage0 (commit, 1 arrival)
    const uint32_t mb_e1 = smem_base + 40;   // empty stage1
    float* bias_s = reinterpret_cast<float*>(sm + 64);
    const uint32_t tiles = (smem_base + 512 + 1023) & ~1023u;   // 1024-aligned B base
    char* tbase = sm + (tiles - smem_base);

    const int tid = threadIdx.x;
    const int wid = tid >> 5, lid = tid & 31;
    const long rowbase = (long)blockIdx.x * TILE_M;

    if (wid == 12) {
        T5_ALLOC(smem_base, TMEM_COLS);
        T5_RELINQ();
    }
    if (tid == 0) {
        mbar_init(mb_f0, 384); mbar_init(mb_f1, 384);
        mbar_init(mb_e0, 1);   mbar_init(mb_e1, 1);
    }
    if (tid < EE) bias_s[tid] = bias[tid];
    __syncthreads();
    const uint32_t tmem = *reinterpret_cast<uint32_t*>(sm);

    if (wid < 8) {
        // ===== A producers: 2 threads/row (8 warps), convert fp32 -> 3x bf16 -> TMEM =====
        const int awid  = wid & 3;              // subpartition
        const int khalf = wid >> 2;             // which 32-k half of the chunk
        const int row   = awid * 32 + lid;
        const uint32_t woff = (uint32_t)awid << 21;
        const uint32_t ccol = (uint32_t)khalf * 16;   // col offset within 32-col term
        const float4* xg = reinterpret_cast<const float4*>(x) +
                           (size_t)(rowbase + row) * (DD / 4) + khalf * 8;

        int pph[2] = {1, 1};
        for (int c = 0; c < NCH; c++) {
            // issue x loads BEFORE the empty wait (latency hidden by wait)
            float4 f4[8];
#pragma unroll
            for (int i = 0; i < 8; i++) f4[i] = xg[c * 16 + i];

            const int stage = c & 1;
            mbar_wait(stage ? mb_e1 : mb_e0, pph[stage]);
            pph[stage] ^= 1;

            const uint32_t acol = tmem + TM_A + stage * 96 + woff + ccol;
#pragma unroll
            for (int g = 0; g < 2; g++) {
                uint32_t h8[8], m8[8], l8[8];
#pragma unroll
                for (int i = 0; i < 4; i++) {
                    float4 v = f4[g * 4 + i];
#pragma unroll
                    for (int p = 0; p < 2; p++) {
                        float a0 = p ? v.z : v.x;
                        float a1 = p ? v.w : v.y;
                        __nv_bfloat162 H = __float22bfloat162_rn(make_float2(a0, a1));
                        float2 Hf = __bfloat1622float2(H);
                        float r0 = a0 - Hf.x, r1 = a1 - Hf.y;
                        __nv_bfloat162 M = __float22bfloat162_rn(make_float2(r0, r1));
                        float2 Mf = __bfloat1622float2(M);
                        __nv_bfloat162 L = __float22bfloat162_rn(make_float2(r0 - Mf.x, r1 - Mf.y));
                        h8[i * 2 + p] = *reinterpret_cast<uint32_t*>(&H);
                        m8[i * 2 + p] = *reinterpret_cast<uint32_t*>(&M);
                        l8[i * 2 + p] = *reinterpret_cast<uint32_t*>(&L);
                    }
                }
                STTM8(acol + 0 * 32 + g * 8, h8);
                STTM8(acol + 1 * 32 + g * 8, m8);
                STTM8(acol + 2 * 32 + g * 8, l8);
            }
            T5_WAIT_ST();
            T5_FENCE_BEFORE();
            mbar_arrive(stage ? mb_f1 : mb_f0);
        }

        // ===== epilogue (warps 0-3 only): wait last commit, read D, softmax =====
        if (wid < 4) {
            mbar_wait(mb_e1, 1);
            T5_FENCE_AFTER();

            float vals[EE];
            {
                uint32_t a[32];
                LDTM32(a, tmem + TM_D);
                T5_WAIT_LD();
#pragma unroll
                for (int e = 0; e < 32; e++)
                    vals[e] = __uint_as_float(a[e]) + bias_s[e];
                LDTM32(a, tmem + TM_D + 32);
                T5_WAIT_LD();
#pragma unroll
                for (int e = 0; e < 32; e++)
                    vals[32 + e] = __uint_as_float(a[e]) + bias_s[32 + e];
            }
            T5_FENCE_BEFORE();

            float bv = vals[0];
            int be = 0;
#pragma unroll
            for (int e = 1; e < EE; e++)
                if (vals[e] > bv) { bv = vals[e]; be = e; }
            float s = 0.f;
#pragma unroll
            for (int e = 0; e < EE; e++)
                s += __expf(vals[e] - bv);

            long r = rowbase + wid * 32 + lid;
            g_p0[r]  = __expf(vals[0] - bv) / s;
            g_idx[r] = be;
        }
    } else if (wid < 12) {
        // ===== B producers: stream W bf16 chunks into SMEM (SW128), uint4 path =====
        const int bt = tid - 256;   // 0..127
        const uint4* wh4 = reinterpret_cast<const uint4*>(g_wh);
        const uint4* wm4 = reinterpret_cast<const uint4*>(g_wm);
        const uint4* wl4 = reinterpret_cast<const uint4*>(g_wl);

        // per chunk: 512 uint4 per term, 4 per thread per term
        uint4 pre[12];
        {
            // prefetch chunk 0
#pragma unroll
            for (int q = 0; q < 4; q++) {
                int j = bt + q * 128;           // 0..511
                int br = j >> 3, bk = j & 7;    // row, 16B-col
                size_t gi = (size_t)br * (DD / 8) + bk;   // +c*8 per chunk (c=0)
                pre[q]     = wh4[gi];
                pre[4 + q] = wm4[gi];
                pre[8 + q] = wl4[gi];
            }
        }

        int pph[2] = {1, 1};
        for (int c = 0; c < NCH; c++) {
            const int stage = c & 1;
            mbar_wait(stage ? mb_e1 : mb_e0, pph[stage]);
            pph[stage] ^= 1;

            char* bs = tbase + stage * B_STAGE_B;
#pragma unroll
            for (int q = 0; q < 4; q++) {
                int j = bt + q * 128;
                int br = j >> 3, bk = j & 7;
                uint32_t sw = sw128((uint32_t)br * 128 + bk * 16);
                *reinterpret_cast<uint4*>(bs + sw)                = pre[q];
                *reinterpret_cast<uint4*>(bs + B_TILE_B + sw)     = pre[4 + q];
                *reinterpret_cast<uint4*>(bs + 2 * B_TILE_B + sw) = pre[8 + q];
            }
            FENCE_ASYNC();
            mbar_arrive(stage ? mb_f1 : mb_f0);

            // prefetch next chunk (latency hidden behind next empty-wait)
            if (c + 1 < NCH) {
#pragma unroll
                for (int q = 0; q < 4; q++) {
                    int j = bt + q * 128;
                    int br = j >> 3, bk = j & 7;
                    size_t gi = (size_t)br * (DD / 8) + (c + 1) * 8 + bk;
                    pre[q]     = wh4[gi];
                    pre[4 + q] = wm4[gi];
                    pre[8 + q] = wl4[gi];
                }
            }
        }
    } else {
        // ===== MMA warp (warp 12) =====
        if (elect1()) {
            const int ta[6] = {0, 0, 1, 1, 0, 2};
            const int tb[6] = {0, 1, 0, 1, 2, 0};
            int cph[2] = {0, 0};
            for (int c = 0; c < NCH; c++) {
                const int stage = c & 1;
                mbar_wait(stage ? mb_f1 : mb_f0, cph[stage]);
                cph[stage] ^= 1;
                T5_FENCE_AFTER();

                uint64_t bd[3];
#pragma unroll
                for (int t = 0; t < 3; t++)
                    bd[t] = make_desc_sw128(tiles + stage * B_STAGE_B + t * B_TILE_B);
                const uint32_t abase = tmem + TM_A + stage * 96;

#pragma unroll
                for (int ks = 0; ks < 4; ks++) {
#pragma unroll
                    for (int t = 0; t < 6; t++) {
                        uint32_t a = abase + ta[t] * 32 + ks * 8;
                        uint64_t b = bd[tb[t]] + ks * 2;
                        uint32_t en = !(c == 0 && ks == 0 && t == 0);
                        mma_ts_f16(tmem + TM_D, a, b, IDESC, en);
                    }
                }
                t5_commit(stage ? mb_e1 : mb_e0);
            }
        }
    }

    __syncthreads();
    if (wid == 12) {
        T5_DEALLOC(tmem, TMEM_COLS);
    }
#else
    // ---------------- portable fallback (generic-PTX compile phase only) ----------------
    const int tid = threadIdx.x;
    const long rowbase = (long)blockIdx.x * TILE_M;
    if (tid < TILE_M) {
        const float* xr = x + (rowbase + tid) * (size_t)DD;
        float bv = -1e30f;
        int be = 0;
        float vals[EE];
        for (int e = 0; e < EE; e++) {
            float acc = 0.f;
            const float* wr = w + (size_t)e * DD;
            for (int k = 0; k < DD; k++) acc = fmaf(xr[k], wr[k], acc);
            acc += bias[e];
            vals[e] = acc;
            if (acc > bv) { bv = acc; be = e; }
        }
        float s = 0.f;
        for (int e = 0; e < EE; e++) s += __expf(vals[e] - bv);
        long r = rowbase + tid;
        g_p0[r]  = __expf(vals[0] - bv) / s;
        g_idx[r] = be;
    }
#endif
}

// ---------------- Kernel 2: per-batch membership mask -> masked p0 ----------------
__global__ void k2_mask(void) {
    int b    = blockIdx.x * 8 + (threadIdx.x >> 5);
    int lane = threadIdx.x & 31;
    long base = (long)b * NN;
    unsigned long long m = 0ull;
#pragma unroll
    for (int q = 0; q < 4; q++) {
        int v = g_idx[base + lane + 32 * q];
        m |= 1ull << v;
    }
#pragma unroll
    for (int off = 16; off >= 1; off >>= 1)
        m |= __shfl_xor_sync(0xffffffffu, m, off);
#pragma unroll
    for (int h = 0; h < 2; h++) {
        int n = lane + 32 * h;
        g_masked[b * EE + n] = ((m >> n) & 1ull) ? g_p0[base + n] : 0.f;
    }
}

// ---------------- Kernel 3: deterministic column sums (denom, load) ----------------
__global__ void k3_denom(void) {
    __shared__ float sv[256];
    __shared__ int   sc[256];
    int n = blockIdx.x;
    int t = threadIdx.x;
    float s = 0.f;
    int cnt = 0;
    for (int k = 0; k < BB / 256; k++) {
        float v = g_masked[(size_t)(t + k * 256) * EE + n];
        s += v;
        cnt += (v > 0.f);
    }
    sv[t] = s; sc[t] = cnt;
    __syncthreads();
    for (int off = 128; off >= 1; off >>= 1) {
        if (t < off) { sv[t] += sv[t + off]; sc[t] += sc[t + off]; }
        __syncthreads();
    }
    if (t == 0) {
        g_denom[n] = sv[0] + EPS;
        g_load[n]  = sc[0];
    }
}

// ---------------- Kernel 4 (sparse): write only the nonzero gs entries ----------------
// gs[b, n, 0] for n < 64; everything else pre-zeroed by cudaMemsetAsync.
__global__ void k4_sparse(float* __restrict__ out) {
    int i = blockIdx.x * blockDim.x + threadIdx.x;   // 0..131071
    int b = i >> 6;
    int n = i & 63;
    float m = g_masked[b * EE + n];
    out[((size_t)b * NN + n) * EE] = m * (CAPACITY / g_denom[n]);
}

// ---------------- Kernel 5: loss ----------------
__global__ void k5_loss(float* __restrict__ lossptr) {
    double si = 0.0, si2 = 0.0, sl = 0.0, sl2 = 0.0;
    for (int n = 0; n < EE; n++) {
        double dn = (double)g_denom[n];
        double S  = dn - (double)EPS;
        double imp = (double)CAPACITY * S / dn;
        si  += imp;
        si2 += imp * imp;
        double ld = (double)g_load[n];
        sl  += ld;
        sl2 += ld * ld;
    }
    const double M = (double)(NN * EE);
    double mean_i = si / M;
    double var_i  = (si2 - si * si / M) / (M - 1.0);
    double cv_i   = var_i / (mean_i * mean_i + 1e-10);
    double mean_l = sl / M;
    double var_l  = (sl2 - sl * sl / M) / (M - 1.0);
    double cv_l   = var_l / (mean_l * mean_l + 1e-10);
    *lossptr = (float)(cv_i + cv_l);
}

extern "C" void kernel_launch(void* const* d_in, const int* in_sizes, int n_in,
                              void* d_out, int out_size) {
    const float* x    = (const float*)d_in[0];
    const float* w    = (const float*)d_in[1];
    const float* bias = (const float*)d_in[2];
    float* out = (float*)d_out;

    cudaFuncSetAttribute(k1_gemm, cudaFuncAttributeMaxDynamicSharedMemorySize, SMEM_TC);

    // 3 small launches first so k1 is the 4th kernel launch (ncu capture slot)
    k0h<<<(EE * DD) / 256, 256>>>(w);
    k0m<<<(EE * DD) / 256, 256>>>(w);
    k0l<<<(EE * DD) / 256, 256>>>(w);
    k1_gemm<<<ROWS / TILE_M, THREADS1, SMEM_TC>>>(x, w, bias);
    k2_mask<<<BB / 8, 256>>>();
    k3_denom<<<EE, 256>>>();

    const long total = (long)BB * NN * EE;        // 16777216
    if ((long)out_size >= total) {
        cudaMemsetAsync(out, 0, total * sizeof(float));
        k4_sparse<<<(BB * EE) / 256, 256>>>(out);
    }
    if ((long)out_size > total) {
        k5_loss<<<1, 1>>>(out + total);
    } else if ((long)out_size < total) {
        k5_loss<<<1, 1>>>(out);
    }
}